// round 1
// baseline (speedup 1.0000x reference)
#include <cuda_runtime.h>
#include <float.h>

// Problem constants (fixed shapes)
#define NN 50000
#define NE 800000
#define INF_ 512
#define HID 256
#define NH 8
#define HD 32
#define NCLS 40
#define NEG_SLOPE 0.2f

// ---------------- scratch (device globals; no allocs allowed) ----------------
__device__ __align__(16) float g_feat[NN * HID];
__device__ __align__(16) float g_h[NN * HID];
__device__ __align__(16) float g_feat2[NN * NCLS];
__device__ __align__(16) float g_el[NN * NH];
__device__ __align__(16) float g_er[NN * NH];
__device__ __align__(16) float g_el2[NN];
__device__ __align__(16) float g_er2[NN];
__device__ int g_deg[NN];
__device__ int g_cursor[NN];
__device__ int g_rowptr[NN + 1];
__device__ int g_esrc[NE];

// ---------------- CSR build ----------------
__global__ void k_zero(int* p, int n) {
    int i = blockIdx.x * blockDim.x + threadIdx.x;
    if (i < n) p[i] = 0;
}

__global__ void k_hist(const int* __restrict__ dst, int* deg, int E) {
    int i = blockIdx.x * blockDim.x + threadIdx.x;
    if (i < E) atomicAdd(&deg[dst[i]], 1);
}

// single-block exclusive scan over 50k elements
__global__ void k_scan(const int* __restrict__ deg, int* __restrict__ rowptr, int n) {
    __shared__ int wsum[32];
    __shared__ int carry;
    int t = threadIdx.x, lane = t & 31, wid = t >> 5;
    if (t == 0) carry = 0;
    __syncthreads();
    for (int base = 0; base < n; base += blockDim.x) {
        int i = base + t;
        int v = (i < n) ? deg[i] : 0;
        int x = v;
#pragma unroll
        for (int o = 1; o < 32; o <<= 1) {
            int y = __shfl_up_sync(0xffffffffu, x, o);
            if (lane >= o) x += y;
        }
        if (lane == 31) wsum[wid] = x;
        __syncthreads();
        if (wid == 0) {
            int s = (lane < (int)(blockDim.x >> 5)) ? wsum[lane] : 0;
#pragma unroll
            for (int o = 1; o < 32; o <<= 1) {
                int y = __shfl_up_sync(0xffffffffu, s, o);
                if (lane >= o) s += y;
            }
            wsum[lane] = s;  // inclusive warp-sums scan
        }
        __syncthreads();
        int woff = (wid == 0) ? 0 : wsum[wid - 1];
        int excl = carry + woff + x - v;
        if (i < n) rowptr[i] = excl;
        int total = wsum[(blockDim.x >> 5) - 1];
        __syncthreads();
        if (t == 0) carry += total;
        __syncthreads();
    }
    if (threadIdx.x == 0) rowptr[n] = carry;
}

__global__ void k_copy(int* __restrict__ d, const int* __restrict__ s, int n) {
    int i = blockIdx.x * blockDim.x + threadIdx.x;
    if (i < n) d[i] = s[i];
}

__global__ void k_scatter(const int* __restrict__ dst, const int* __restrict__ src,
                          int* cursor, int* __restrict__ esrc, int E) {
    int i = blockIdx.x * blockDim.x + threadIdx.x;
    if (i < E) {
        int p = atomicAdd(&cursor[dst[i]], 1);
        esrc[p] = src[i];
    }
}

// ---------------- SGEMM: C[M,N] = A[M,K] @ B[K,N], fp32 ----------------
// 128x64 block tile, BK=16, 256 threads, 8x4 per-thread microtile.
#define BM 128
#define BN 64
#define BK 16

__global__ void __launch_bounds__(256) k_sgemm(const float* __restrict__ A,
                                               const float* __restrict__ B,
                                               float* __restrict__ C,
                                               int M, int N, int K) {
    __shared__ float As[BK][BM];
    __shared__ float Bs[BK][BN];
    int tid = threadIdx.x;
    int tx = tid & 15;   // N direction
    int ty = tid >> 4;   // M direction
    int m0 = blockIdx.x * BM, n0 = blockIdx.y * BN;

    int arow0 = tid >> 2;            // 0..63
    int ak = (tid & 3) * 4;          // 0,4,8,12
    int arow1 = arow0 + 64;
    int brow = tid >> 4;             // 0..15
    int bcol = (tid & 15) * 4;       // 0..60

    float acc[8][4];
#pragma unroll
    for (int i = 0; i < 8; i++)
#pragma unroll
        for (int j = 0; j < 4; j++) acc[i][j] = 0.f;

    for (int k0 = 0; k0 < K; k0 += BK) {
        float4 a0 = make_float4(0.f, 0.f, 0.f, 0.f), a1 = a0, b0 = a0;
        if (m0 + arow0 < M) a0 = *(const float4*)(A + (size_t)(m0 + arow0) * K + k0 + ak);
        if (m0 + arow1 < M) a1 = *(const float4*)(A + (size_t)(m0 + arow1) * K + k0 + ak);
        if (n0 + bcol < N)  b0 = *(const float4*)(B + (size_t)(k0 + brow) * N + n0 + bcol);
        __syncthreads();
        As[ak + 0][arow0] = a0.x; As[ak + 1][arow0] = a0.y;
        As[ak + 2][arow0] = a0.z; As[ak + 3][arow0] = a0.w;
        As[ak + 0][arow1] = a1.x; As[ak + 1][arow1] = a1.y;
        As[ak + 2][arow1] = a1.z; As[ak + 3][arow1] = a1.w;
        *(float4*)&Bs[brow][bcol] = b0;
        __syncthreads();
#pragma unroll
        for (int kk = 0; kk < BK; kk++) {
            float a[8], b[4];
#pragma unroll
            for (int i = 0; i < 8; i++) a[i] = As[kk][ty * 8 + i];
#pragma unroll
            for (int j = 0; j < 4; j++) b[j] = Bs[kk][tx * 4 + j];
#pragma unroll
            for (int i = 0; i < 8; i++)
#pragma unroll
                for (int j = 0; j < 4; j++) acc[i][j] = fmaf(a[i], b[j], acc[i][j]);
        }
    }
#pragma unroll
    for (int i = 0; i < 8; i++) {
        int r = m0 + ty * 8 + i;
        if (r >= M) continue;
#pragma unroll
        for (int j = 0; j < 4; j++) {
            int c = n0 + tx * 4 + j;
            if (c < N) C[(size_t)r * N + c] = acc[i][j];
        }
    }
}

// ---------------- el/er projections ----------------
__device__ __forceinline__ float warp_sum(float v) {
#pragma unroll
    for (int o = 16; o > 0; o >>= 1) v += __shfl_xor_sync(0xffffffffu, v, o);
    return v;
}
__device__ __forceinline__ float warp_max(float v) {
#pragma unroll
    for (int o = 16; o > 0; o >>= 1) v = fmaxf(v, __shfl_xor_sync(0xffffffffu, v, o));
    return v;
}
__device__ __forceinline__ float leaky(float x) { return x > 0.f ? x : NEG_SLOPE * x; }

// one warp per node, 8 heads x 32 dims
__global__ void k_elr8(const float* __restrict__ feat, const float* __restrict__ al,
                       const float* __restrict__ ar, float* __restrict__ el,
                       float* __restrict__ er, int n) {
    int w = (blockIdx.x * blockDim.x + threadIdx.x) >> 5;
    int lane = threadIdx.x & 31;
    if (w >= n) return;
    const float* f = feat + (size_t)w * HID;
    float sl[NH], sr[NH];
#pragma unroll
    for (int j = 0; j < NH; j++) {
        float v = f[j * 32 + lane];
        sl[j] = v * __ldg(al + j * 32 + lane);
        sr[j] = v * __ldg(ar + j * 32 + lane);
    }
#pragma unroll
    for (int j = 0; j < NH; j++) { sl[j] = warp_sum(sl[j]); sr[j] = warp_sum(sr[j]); }
    if (lane == 0) {
#pragma unroll
        for (int j = 0; j < NH; j++) {
            el[w * NH + j] = sl[j];
            er[w * NH + j] = sr[j];
        }
    }
}

__global__ void k_elr1(const float* __restrict__ feat2, const float* __restrict__ al,
                       const float* __restrict__ ar, float* __restrict__ el,
                       float* __restrict__ er, int n) {
    int w = (blockIdx.x * blockDim.x + threadIdx.x) >> 5;
    int lane = threadIdx.x & 31;
    if (w >= n) return;
    const float* f = feat2 + (size_t)w * NCLS;
    float sl = f[lane] * __ldg(al + lane);
    float sr = f[lane] * __ldg(ar + lane);
    if (lane < 8) {
        sl += f[32 + lane] * __ldg(al + 32 + lane);
        sr += f[32 + lane] * __ldg(ar + 32 + lane);
    }
    sl = warp_sum(sl);
    sr = warp_sum(sr);
    if (lane == 0) { el[w] = sl; er[w] = sr; }
}

// ---------------- aggregation: one warp per dst node ----------------
__global__ void k_agg8(const float* __restrict__ feat, const float* __restrict__ el,
                       const float* __restrict__ er, const int* __restrict__ rowptr,
                       const int* __restrict__ esrc, const float* __restrict__ bias,
                       float* __restrict__ out, int n, int do_relu) {
    int node = (blockIdx.x * blockDim.x + threadIdx.x) >> 5;
    int lane = threadIdx.x & 31;
    if (node >= n) return;
    int beg = rowptr[node], end = rowptr[node + 1];

    float4 e0 = *(const float4*)(er + node * NH);
    float4 e1 = *(const float4*)(er + node * NH + 4);
    float ern[NH] = {e0.x, e0.y, e0.z, e0.w, e1.x, e1.y, e1.z, e1.w};

    // phase A: per-head max over incoming edges
    float mx[NH];
#pragma unroll
    for (int j = 0; j < NH; j++) mx[j] = -FLT_MAX;
    for (int i = beg + lane; i < end; i += 32) {
        int s = esrc[i];
        float4 a0 = *(const float4*)(el + s * NH);
        float4 a1 = *(const float4*)(el + s * NH + 4);
        float ev[NH] = {a0.x, a0.y, a0.z, a0.w, a1.x, a1.y, a1.z, a1.w};
#pragma unroll
        for (int j = 0; j < NH; j++) mx[j] = fmaxf(mx[j], leaky(ev[j] + ern[j]));
    }
#pragma unroll
    for (int j = 0; j < NH; j++) mx[j] = warp_max(mx[j]);

    // phase B: denominators
    float den[NH];
#pragma unroll
    for (int j = 0; j < NH; j++) den[j] = 0.f;
    for (int i = beg + lane; i < end; i += 32) {
        int s = esrc[i];
        float4 a0 = *(const float4*)(el + s * NH);
        float4 a1 = *(const float4*)(el + s * NH + 4);
        float ev[NH] = {a0.x, a0.y, a0.z, a0.w, a1.x, a1.y, a1.z, a1.w};
#pragma unroll
        for (int j = 0; j < NH; j++) den[j] += __expf(leaky(ev[j] + ern[j]) - mx[j]);
    }
    float inv[NH];
#pragma unroll
    for (int j = 0; j < NH; j++) {
        den[j] = warp_sum(den[j]);
        inv[j] = 1.f / fmaxf(den[j], 1e-9f);
    }

    // phase C: weighted gather; lane = feature dim within head
    float acc[NH];
#pragma unroll
    for (int j = 0; j < NH; j++) acc[j] = 0.f;
    for (int i = beg; i < end; i++) {
        int s = esrc[i];                                   // warp-uniform
        float4 a0 = *(const float4*)(el + s * NH);
        float4 a1 = *(const float4*)(el + s * NH + 4);
        float ev[NH] = {a0.x, a0.y, a0.z, a0.w, a1.x, a1.y, a1.z, a1.w};
        const float* fp = feat + (size_t)s * HID;
#pragma unroll
        for (int j = 0; j < NH; j++) {
            float w = __expf(leaky(ev[j] + ern[j]) - mx[j]) * inv[j];
            acc[j] = fmaf(w, fp[j * 32 + lane], acc[j]);
        }
    }
#pragma unroll
    for (int j = 0; j < NH; j++) {
        float v = acc[j] + __ldg(bias + j * 32 + lane);
        if (do_relu) v = fmaxf(v, 0.f);
        out[(size_t)node * HID + j * 32 + lane] = v;
    }
}

// output layer: 1 head, 40 dims
__global__ void k_agg1(const float* __restrict__ feat2, const float* __restrict__ el,
                       const float* __restrict__ er, const int* __restrict__ rowptr,
                       const int* __restrict__ esrc, const float* __restrict__ bias,
                       float* __restrict__ out, int n) {
    int node = (blockIdx.x * blockDim.x + threadIdx.x) >> 5;
    int lane = threadIdx.x & 31;
    if (node >= n) return;
    int beg = rowptr[node], end = rowptr[node + 1];
    float ern = er[node];

    float mx = -FLT_MAX;
    for (int i = beg + lane; i < end; i += 32)
        mx = fmaxf(mx, leaky(el[esrc[i]] + ern));
    mx = warp_max(mx);

    float den = 0.f;
    for (int i = beg + lane; i < end; i += 32)
        den += __expf(leaky(el[esrc[i]] + ern) - mx);
    den = warp_sum(den);
    float inv = 1.f / fmaxf(den, 1e-9f);

    float acc0 = 0.f, acc1 = 0.f;
    for (int i = beg; i < end; i++) {
        int s = esrc[i];
        float w = __expf(leaky(el[s] + ern) - mx) * inv;
        const float* fp = feat2 + (size_t)s * NCLS;
        acc0 = fmaf(w, fp[lane < NCLS ? lane : 0], acc0);
        if (lane < NCLS - 32) acc1 = fmaf(w, fp[32 + lane], acc1);
    }
    if (lane < 32) out[(size_t)node * NCLS + lane] = acc0 + __ldg(bias + lane);
    if (lane < NCLS - 32)
        out[(size_t)node * NCLS + 32 + lane] = acc1 + __ldg(bias + 32 + lane);
}

// ---------------- host ----------------
extern "C" void kernel_launch(void* const* d_in, const int* in_sizes, int n_in,
                              void* d_out, int out_size) {
    const float* in_feat = (const float*)d_in[0];
    const int*   src     = (const int*)d_in[1];
    const int*   dst     = (const int*)d_in[2];
    const float* W0  = (const float*)d_in[3];
    const float* al0 = (const float*)d_in[4];
    const float* ar0 = (const float*)d_in[5];
    const float* b0  = (const float*)d_in[6];
    const float* W1  = (const float*)d_in[7];
    const float* al1 = (const float*)d_in[8];
    const float* ar1 = (const float*)d_in[9];
    const float* b1  = (const float*)d_in[10];
    const float* W2  = (const float*)d_in[11];
    const float* al2 = (const float*)d_in[12];
    const float* ar2 = (const float*)d_in[13];
    const float* b2  = (const float*)d_in[14];
    float* out = (float*)d_out;

    int n = NN;
    int E = in_sizes[1];

    float *feat, *h, *feat2, *el, *er, *el2, *er2;
    int *deg, *cur, *rp, *esrc;
    cudaGetSymbolAddress((void**)&feat, g_feat);
    cudaGetSymbolAddress((void**)&h, g_h);
    cudaGetSymbolAddress((void**)&feat2, g_feat2);
    cudaGetSymbolAddress((void**)&el, g_el);
    cudaGetSymbolAddress((void**)&er, g_er);
    cudaGetSymbolAddress((void**)&el2, g_el2);
    cudaGetSymbolAddress((void**)&er2, g_er2);
    cudaGetSymbolAddress((void**)&deg, g_deg);
    cudaGetSymbolAddress((void**)&cur, g_cursor);
    cudaGetSymbolAddress((void**)&rp, g_rowptr);
    cudaGetSymbolAddress((void**)&esrc, g_esrc);

    // CSR by dst (edge structure constant across layers)
    k_zero<<<(n + 255) / 256, 256>>>(deg, n);
    k_hist<<<(E + 255) / 256, 256>>>(dst, deg, E);
    k_scan<<<1, 1024>>>(deg, rp, n);
    k_copy<<<(n + 255) / 256, 256>>>(cur, rp, n);
    k_scatter<<<(E + 255) / 256, 256>>>(dst, src, cur, esrc, E);

    int nwarp_blocks = (n + 7) / 8;

    // layer 0
    {
        dim3 g((n + BM - 1) / BM, (HID + BN - 1) / BN);
        k_sgemm<<<g, 256>>>(in_feat, W0, feat, n, HID, INF_);
        k_elr8<<<nwarp_blocks, 256>>>(feat, al0, ar0, el, er, n);
        k_agg8<<<nwarp_blocks, 256>>>(feat, el, er, rp, esrc, b0, h, n, 1);
    }
    // layer 1
    {
        dim3 g((n + BM - 1) / BM, (HID + BN - 1) / BN);
        k_sgemm<<<g, 256>>>(h, W1, feat, n, HID, HID);
        k_elr8<<<nwarp_blocks, 256>>>(feat, al1, ar1, el, er, n);
        k_agg8<<<nwarp_blocks, 256>>>(feat, el, er, rp, esrc, b1, h, n, 1);
    }
    // output layer (1 head, 40 classes)
    {
        dim3 g((n + BM - 1) / BM, (NCLS + BN - 1) / BN);
        k_sgemm<<<g, 256>>>(h, W2, feat2, n, NCLS, HID);
        k_elr1<<<nwarp_blocks, 256>>>(feat2, al2, ar2, el2, er2, n);
        k_agg1<<<nwarp_blocks, 256>>>(feat2, el2, er2, rp, esrc, b2, out, n);
    }
}

// round 5
// speedup vs baseline: 1.3980x; 1.3980x over previous
#include <cuda_runtime.h>
#include <float.h>
#include <stdint.h>

// Problem constants (fixed shapes)
#define NN 50000
#define NE 800000
#define INF_ 512
#define HID 256
#define NH 8
#define HD 32
#define NCLS 40
#define NEG_SLOPE 0.2f

// ---------------- scratch (device globals; no allocs allowed) ----------------
__device__ __align__(16) float g_feat[NN * HID];
__device__ __align__(16) float g_h[NN * HID];
__device__ __align__(16) float g_feat2[NN * NCLS];
__device__ __align__(16) float g_el[NN * NH];
__device__ __align__(16) float g_er[NN * NH];
__device__ __align__(16) float g_el2[NN];
__device__ __align__(16) float g_er2[NN];
__device__ int g_deg[NN];
__device__ int g_cursor[NN];
__device__ int g_rowptr[NN + 1];
__device__ int g_esrc[NE];

// ---------------- CSR build ----------------
__global__ void k_zero(int* p, int n) {
    int i = blockIdx.x * blockDim.x + threadIdx.x;
    if (i < n) p[i] = 0;
}

__global__ void k_hist(const int* __restrict__ dst, int* deg, int E) {
    int i = blockIdx.x * blockDim.x + threadIdx.x;
    if (i < E) atomicAdd(&deg[dst[i]], 1);
}

// single-block exclusive scan over 50k elements
__global__ void k_scan(const int* __restrict__ deg, int* __restrict__ rowptr, int n) {
    __shared__ int wsum[32];
    __shared__ int carry;
    int t = threadIdx.x, lane = t & 31, wid = t >> 5;
    if (t == 0) carry = 0;
    __syncthreads();
    for (int base = 0; base < n; base += blockDim.x) {
        int i = base + t;
        int v = (i < n) ? deg[i] : 0;
        int x = v;
#pragma unroll
        for (int o = 1; o < 32; o <<= 1) {
            int y = __shfl_up_sync(0xffffffffu, x, o);
            if (lane >= o) x += y;
        }
        if (lane == 31) wsum[wid] = x;
        __syncthreads();
        if (wid == 0) {
            int s = (lane < (int)(blockDim.x >> 5)) ? wsum[lane] : 0;
#pragma unroll
            for (int o = 1; o < 32; o <<= 1) {
                int y = __shfl_up_sync(0xffffffffu, s, o);
                if (lane >= o) s += y;
            }
            wsum[lane] = s;  // inclusive warp-sums scan
        }
        __syncthreads();
        int woff = (wid == 0) ? 0 : wsum[wid - 1];
        int excl = carry + woff + x - v;
        if (i < n) rowptr[i] = excl;
        int total = wsum[(blockDim.x >> 5) - 1];
        __syncthreads();
        if (t == 0) carry += total;
        __syncthreads();
    }
    if (threadIdx.x == 0) rowptr[n] = carry;
}

__global__ void k_copy(int* __restrict__ d, const int* __restrict__ s, int n) {
    int i = blockIdx.x * blockDim.x + threadIdx.x;
    if (i < n) d[i] = s[i];
}

__global__ void k_scatter(const int* __restrict__ dst, const int* __restrict__ src,
                          int* cursor, int* __restrict__ esrc, int E) {
    int i = blockIdx.x * blockDim.x + threadIdx.x;
    if (i < E) {
        int p = atomicAdd(&cursor[dst[i]], 1);
        esrc[p] = src[i];
    }
}

// ---------------- TF32 tensor-core GEMM: C[M,N] = A[M,K] @ B[K,N] ----------------
// Block tile 128x128, BK=16, 8 warps (2x4) each computing 64x32 via m16n8k8 mma.
#define BM 128
#define BN 128
#define BK 16
#define BMP (BM + 4)
#define BNP (BN + 4)

__device__ __forceinline__ uint32_t f2tf(float f) {
    uint32_t u;
    asm("cvt.rna.tf32.f32 %0, %1;" : "=r"(u) : "f"(f));
    return u;
}

__device__ __forceinline__ void mma8(float* c, const uint32_t* a, const uint32_t* b) {
    asm volatile(
        "mma.sync.aligned.m16n8k8.row.col.f32.tf32.tf32.f32 "
        "{%0,%1,%2,%3}, {%4,%5,%6,%7}, {%8,%9}, {%0,%1,%2,%3};"
        : "+f"(c[0]), "+f"(c[1]), "+f"(c[2]), "+f"(c[3])
        : "r"(a[0]), "r"(a[1]), "r"(a[2]), "r"(a[3]), "r"(b[0]), "r"(b[1]));
}

__global__ void __launch_bounds__(256) k_mma(const float* __restrict__ A,
                                             const float* __restrict__ B,
                                             float* __restrict__ C,
                                             int M, int N, int K) {
    __shared__ uint32_t As[2][BK][BMP];
    __shared__ uint32_t Bs[2][BK][BNP];

    int tid = threadIdx.x;
    int warp = tid >> 5, lane = tid & 31;
    int gid = lane >> 2, tg = lane & 3;
    int wm = warp >> 2, wn = warp & 3;  // warp tile: rows wm*64, cols wn*32
    int m0 = blockIdx.x * BM, n0 = blockIdx.y * BN;

    int arow0 = tid >> 2, arow1 = arow0 + 64, acol = (tid & 3) * 4;
    int brow0 = tid >> 5, brow1 = brow0 + 8, bcol = (tid & 31) * 4;

    float acc[4][4][4];
#pragma unroll
    for (int mi = 0; mi < 4; mi++)
#pragma unroll
        for (int ni = 0; ni < 4; ni++)
#pragma unroll
            for (int r = 0; r < 4; r++) acc[mi][ni][r] = 0.f;

    int kTiles = K / BK;
    float4 ra0, ra1, rb0, rb1;
    const float4 z4 = make_float4(0.f, 0.f, 0.f, 0.f);

    // prefetch tile 0
    {
        int k0 = 0;
        ra0 = (m0 + arow0 < M) ? *(const float4*)(A + (size_t)(m0 + arow0) * K + k0 + acol) : z4;
        ra1 = (m0 + arow1 < M) ? *(const float4*)(A + (size_t)(m0 + arow1) * K + k0 + acol) : z4;
        rb0 = (n0 + bcol < N) ? *(const float4*)(B + (size_t)(k0 + brow0) * N + n0 + bcol) : z4;
        rb1 = (n0 + bcol < N) ? *(const float4*)(B + (size_t)(k0 + brow1) * N + n0 + bcol) : z4;
    }
    // store tile 0
    {
        As[0][acol + 0][arow0] = f2tf(ra0.x); As[0][acol + 1][arow0] = f2tf(ra0.y);
        As[0][acol + 2][arow0] = f2tf(ra0.z); As[0][acol + 3][arow0] = f2tf(ra0.w);
        As[0][acol + 0][arow1] = f2tf(ra1.x); As[0][acol + 1][arow1] = f2tf(ra1.y);
        As[0][acol + 2][arow1] = f2tf(ra1.z); As[0][acol + 3][arow1] = f2tf(ra1.w);
        *(uint4*)&Bs[0][brow0][bcol] =
            make_uint4(f2tf(rb0.x), f2tf(rb0.y), f2tf(rb0.z), f2tf(rb0.w));
        *(uint4*)&Bs[0][brow1][bcol] =
            make_uint4(f2tf(rb1.x), f2tf(rb1.y), f2tf(rb1.z), f2tf(rb1.w));
    }
    __syncthreads();

    int buf = 0;
    for (int kt = 0; kt < kTiles; kt++) {
        if (kt + 1 < kTiles) {
            int k0 = (kt + 1) * BK;
            ra0 = (m0 + arow0 < M) ? *(const float4*)(A + (size_t)(m0 + arow0) * K + k0 + acol) : z4;
            ra1 = (m0 + arow1 < M) ? *(const float4*)(A + (size_t)(m0 + arow1) * K + k0 + acol) : z4;
            rb0 = (n0 + bcol < N) ? *(const float4*)(B + (size_t)(k0 + brow0) * N + n0 + bcol) : z4;
            rb1 = (n0 + bcol < N) ? *(const float4*)(B + (size_t)(k0 + brow1) * N + n0 + bcol) : z4;
        }
#pragma unroll
        for (int ks = 0; ks < BK; ks += 8) {
            uint32_t af[4][4], bf[4][2];
#pragma unroll
            for (int mi = 0; mi < 4; mi++) {
                int mr = wm * 64 + mi * 16 + gid;
                af[mi][0] = As[buf][ks + tg][mr];
                af[mi][1] = As[buf][ks + tg][mr + 8];
                af[mi][2] = As[buf][ks + tg + 4][mr];
                af[mi][3] = As[buf][ks + tg + 4][mr + 8];
            }
#pragma unroll
            for (int ni = 0; ni < 4; ni++) {
                int nc = wn * 32 + ni * 8 + gid;
                bf[ni][0] = Bs[buf][ks + tg][nc];
                bf[ni][1] = Bs[buf][ks + tg + 4][nc];
            }
#pragma unroll
            for (int mi = 0; mi < 4; mi++)
#pragma unroll
                for (int ni = 0; ni < 4; ni++) mma8(acc[mi][ni], af[mi], bf[ni]);
        }
        if (kt + 1 < kTiles) {
            int nb = buf ^ 1;
            As[nb][acol + 0][arow0] = f2tf(ra0.x); As[nb][acol + 1][arow0] = f2tf(ra0.y);
            As[nb][acol + 2][arow0] = f2tf(ra0.z); As[nb][acol + 3][arow0] = f2tf(ra0.w);
            As[nb][acol + 0][arow1] = f2tf(ra1.x); As[nb][acol + 1][arow1] = f2tf(ra1.y);
            As[nb][acol + 2][arow1] = f2tf(ra1.z); As[nb][acol + 3][arow1] = f2tf(ra1.w);
            *(uint4*)&Bs[nb][brow0][bcol] =
                make_uint4(f2tf(rb0.x), f2tf(rb0.y), f2tf(rb0.z), f2tf(rb0.w));
            *(uint4*)&Bs[nb][brow1][bcol] =
                make_uint4(f2tf(rb1.x), f2tf(rb1.y), f2tf(rb1.z), f2tf(rb1.w));
            __syncthreads();
            buf ^= 1;
        }
    }

    // epilogue
#pragma unroll
    for (int mi = 0; mi < 4; mi++) {
        int r0 = m0 + wm * 64 + mi * 16 + gid;
#pragma unroll
        for (int ni = 0; ni < 4; ni++) {
            int c0 = n0 + wn * 32 + ni * 8 + tg * 2;
            if (r0 < M) {
                if (c0 < N) C[(size_t)r0 * N + c0] = acc[mi][ni][0];
                if (c0 + 1 < N) C[(size_t)r0 * N + c0 + 1] = acc[mi][ni][1];
            }
            if (r0 + 8 < M) {
                if (c0 < N) C[(size_t)(r0 + 8) * N + c0] = acc[mi][ni][2];
                if (c0 + 1 < N) C[(size_t)(r0 + 8) * N + c0 + 1] = acc[mi][ni][3];
            }
        }
    }
}

// ---------------- el/er projections ----------------
__device__ __forceinline__ float warp_sum(float v) {
#pragma unroll
    for (int o = 16; o > 0; o >>= 1) v += __shfl_xor_sync(0xffffffffu, v, o);
    return v;
}
__device__ __forceinline__ float warp_max(float v) {
#pragma unroll
    for (int o = 16; o > 0; o >>= 1) v = fmaxf(v, __shfl_xor_sync(0xffffffffu, v, o));
    return v;
}
__device__ __forceinline__ float leaky(float x) { return x > 0.f ? x : NEG_SLOPE * x; }

// one warp per node, 8 heads x 32 dims
__global__ void k_elr8(const float* __restrict__ feat, const float* __restrict__ al,
                       const float* __restrict__ ar, float* __restrict__ el,
                       float* __restrict__ er, int n) {
    int w = (blockIdx.x * blockDim.x + threadIdx.x) >> 5;
    int lane = threadIdx.x & 31;
    if (w >= n) return;
    const float* f = feat + (size_t)w * HID;
    float sl[NH], sr[NH];
#pragma unroll
    for (int j = 0; j < NH; j++) {
        float v = f[j * 32 + lane];
        sl[j] = v * __ldg(al + j * 32 + lane);
        sr[j] = v * __ldg(ar + j * 32 + lane);
    }
#pragma unroll
    for (int j = 0; j < NH; j++) { sl[j] = warp_sum(sl[j]); sr[j] = warp_sum(sr[j]); }
    if (lane == 0) {
#pragma unroll
        for (int j = 0; j < NH; j++) {
            el[w * NH + j] = sl[j];
            er[w * NH + j] = sr[j];
        }
    }
}

__global__ void k_elr1(const float* __restrict__ feat2, const float* __restrict__ al,
                       const float* __restrict__ ar, float* __restrict__ el,
                       float* __restrict__ er, int n) {
    int w = (blockIdx.x * blockDim.x + threadIdx.x) >> 5;
    int lane = threadIdx.x & 31;
    if (w >= n) return;
    const float* f = feat2 + (size_t)w * NCLS;
    float sl = f[lane] * __ldg(al + lane);
    float sr = f[lane] * __ldg(ar + lane);
    if (lane < 8) {
        sl += f[32 + lane] * __ldg(al + 32 + lane);
        sr += f[32 + lane] * __ldg(ar + 32 + lane);
    }
    sl = warp_sum(sl);
    sr = warp_sum(sr);
    if (lane == 0) { el[w] = sl; er[w] = sr; }
}

// ---------------- aggregation: one warp per dst node ----------------
__global__ void k_agg8(const float* __restrict__ feat, const float* __restrict__ el,
                       const float* __restrict__ er, const int* __restrict__ rowptr,
                       const int* __restrict__ esrc, const float* __restrict__ bias,
                       float* __restrict__ out, int n, int do_relu) {
    int node = (blockIdx.x * blockDim.x + threadIdx.x) >> 5;
    int lane = threadIdx.x & 31;
    if (node >= n) return;
    int beg = rowptr[node], end = rowptr[node + 1];

    float4 e0 = *(const float4*)(er + node * NH);
    float4 e1 = *(const float4*)(er + node * NH + 4);
    float ern[NH] = {e0.x, e0.y, e0.z, e0.w, e1.x, e1.y, e1.z, e1.w};

    // phase A: per-head max over incoming edges
    float mx[NH];
#pragma unroll
    for (int j = 0; j < NH; j++) mx[j] = -FLT_MAX;
    for (int i = beg + lane; i < end; i += 32) {
        int s = esrc[i];
        float4 a0 = *(const float4*)(el + s * NH);
        float4 a1 = *(const float4*)(el + s * NH + 4);
        float ev[NH] = {a0.x, a0.y, a0.z, a0.w, a1.x, a1.y, a1.z, a1.w};
#pragma unroll
        for (int j = 0; j < NH; j++) mx[j] = fmaxf(mx[j], leaky(ev[j] + ern[j]));
    }
#pragma unroll
    for (int j = 0; j < NH; j++) mx[j] = warp_max(mx[j]);

    // phase B: denominators
    float den[NH];
#pragma unroll
    for (int j = 0; j < NH; j++) den[j] = 0.f;
    for (int i = beg + lane; i < end; i += 32) {
        int s = esrc[i];
        float4 a0 = *(const float4*)(el + s * NH);
        float4 a1 = *(const float4*)(el + s * NH + 4);
        float ev[NH] = {a0.x, a0.y, a0.z, a0.w, a1.x, a1.y, a1.z, a1.w};
#pragma unroll
        for (int j = 0; j < NH; j++) den[j] += __expf(leaky(ev[j] + ern[j]) - mx[j]);
    }
    float inv[NH];
#pragma unroll
    for (int j = 0; j < NH; j++) {
        den[j] = warp_sum(den[j]);
        inv[j] = 1.f / fmaxf(den[j], 1e-9f);
    }

    // phase C: weighted gather; lane = feature dim within head
    float acc[NH];
#pragma unroll
    for (int j = 0; j < NH; j++) acc[j] = 0.f;
    for (int i = beg; i < end; i++) {
        int s = esrc[i];  // warp-uniform
        float4 a0 = *(const float4*)(el + s * NH);
        float4 a1 = *(const float4*)(el + s * NH + 4);
        float ev[NH] = {a0.x, a0.y, a0.z, a0.w, a1.x, a1.y, a1.z, a1.w};
        const float* fp = feat + (size_t)s * HID;
#pragma unroll
        for (int j = 0; j < NH; j++) {
            float w = __expf(leaky(ev[j] + ern[j]) - mx[j]) * inv[j];
            acc[j] = fmaf(w, fp[j * 32 + lane], acc[j]);
        }
    }
#pragma unroll
    for (int j = 0; j < NH; j++) {
        float v = acc[j] + __ldg(bias + j * 32 + lane);
        if (do_relu) v = fmaxf(v, 0.f);
        out[(size_t)node * HID + j * 32 + lane] = v;
    }
}

// output layer: 1 head, 40 dims
__global__ void k_agg1(const float* __restrict__ feat2, const float* __restrict__ el,
                       const float* __restrict__ er, const int* __restrict__ rowptr,
                       const int* __restrict__ esrc, const float* __restrict__ bias,
                       float* __restrict__ out, int n) {
    int node = (blockIdx.x * blockDim.x + threadIdx.x) >> 5;
    int lane = threadIdx.x & 31;
    if (node >= n) return;
    int beg = rowptr[node], end = rowptr[node + 1];
    float ern = er[node];

    float mx = -FLT_MAX;
    for (int i = beg + lane; i < end; i += 32)
        mx = fmaxf(mx, leaky(el[esrc[i]] + ern));
    mx = warp_max(mx);

    float den = 0.f;
    for (int i = beg + lane; i < end; i += 32)
        den += __expf(leaky(el[esrc[i]] + ern) - mx);
    den = warp_sum(den);
    float inv = 1.f / fmaxf(den, 1e-9f);

    float acc0 = 0.f, acc1 = 0.f;
    for (int i = beg; i < end; i++) {
        int s = esrc[i];
        float w = __expf(leaky(el[s] + ern) - mx) * inv;
        const float* fp = feat2 + (size_t)s * NCLS;
        acc0 = fmaf(w, fp[lane < NCLS ? lane : 0], acc0);
        if (lane < NCLS - 32) acc1 = fmaf(w, fp[32 + lane], acc1);
    }
    if (lane < 32) out[(size_t)node * NCLS + lane] = acc0 + __ldg(bias + lane);
    if (lane < NCLS - 32)
        out[(size_t)node * NCLS + 32 + lane] = acc1 + __ldg(bias + 32 + lane);
}

// ---------------- host ----------------
extern "C" void kernel_launch(void* const* d_in, const int* in_sizes, int n_in,
                              void* d_out, int out_size) {
    const float* in_feat = (const float*)d_in[0];
    const int*   src     = (const int*)d_in[1];
    const int*   dst     = (const int*)d_in[2];
    const float* W0  = (const float*)d_in[3];
    const float* al0 = (const float*)d_in[4];
    const float* ar0 = (const float*)d_in[5];
    const float* b0  = (const float*)d_in[6];
    const float* W1  = (const float*)d_in[7];
    const float* al1 = (const float*)d_in[8];
    const float* ar1 = (const float*)d_in[9];
    const float* b1  = (const float*)d_in[10];
    const float* W2  = (const float*)d_in[11];
    const float* al2 = (const float*)d_in[12];
    const float* ar2 = (const float*)d_in[13];
    const float* b2  = (const float*)d_in[14];
    float* out = (float*)d_out;

    int n = NN;
    int E = in_sizes[1];

    float *feat, *h, *feat2, *el, *er, *el2, *er2;
    int *deg, *cur, *rp, *esrc;
    cudaGetSymbolAddress((void**)&feat, g_feat);
    cudaGetSymbolAddress((void**)&h, g_h);
    cudaGetSymbolAddress((void**)&feat2, g_feat2);
    cudaGetSymbolAddress((void**)&el, g_el);
    cudaGetSymbolAddress((void**)&er, g_er);
    cudaGetSymbolAddress((void**)&el2, g_el2);
    cudaGetSymbolAddress((void**)&er2, g_er2);
    cudaGetSymbolAddress((void**)&deg, g_deg);
    cudaGetSymbolAddress((void**)&cur, g_cursor);
    cudaGetSymbolAddress((void**)&rp, g_rowptr);
    cudaGetSymbolAddress((void**)&esrc, g_esrc);

    // CSR by dst (edge structure constant across layers)
    k_zero<<<(n + 255) / 256, 256>>>(deg, n);
    k_hist<<<(E + 255) / 256, 256>>>(dst, deg, E);
    k_scan<<<1, 1024>>>(deg, rp, n);
    k_copy<<<(n + 255) / 256, 256>>>(cur, rp, n);
    k_scatter<<<(E + 255) / 256, 256>>>(dst, src, cur, esrc, E);

    int nwarp_blocks = (n + 7) / 8;

    // layer 0
    {
        dim3 g((n + BM - 1) / BM, (HID + BN - 1) / BN);
        k_mma<<<g, 256>>>(in_feat, W0, feat, n, HID, INF_);
        k_elr8<<<nwarp_blocks, 256>>>(feat, al0, ar0, el, er, n);
        k_agg8<<<nwarp_blocks, 256>>>(feat, el, er, rp, esrc, b0, h, n, 1);
    }
    // layer 1
    {
        dim3 g((n + BM - 1) / BM, (HID + BN - 1) / BN);
        k_mma<<<g, 256>>>(h, W1, feat, n, HID, HID);
        k_elr8<<<nwarp_blocks, 256>>>(feat, al1, ar1, el, er, n);
        k_agg8<<<nwarp_blocks, 256>>>(feat, el, er, rp, esrc, b1, h, n, 1);
    }
    // output layer (1 head, 40 classes)
    {
        dim3 g((n + BM - 1) / BM, (NCLS + BN - 1) / BN);
        k_mma<<<g, 256>>>(h, W2, feat2, n, NCLS, HID);
        k_elr1<<<nwarp_blocks, 256>>>(feat2, al2, ar2, el2, er2, n);
        k_agg1<<<nwarp_blocks, 256>>>(feat2, el2, er2, rp, esrc, b2, out, n);
    }
}

// round 6
// speedup vs baseline: 1.6844x; 1.2048x over previous
#include <cuda_runtime.h>
#include <float.h>
#include <stdint.h>

// Problem constants (fixed shapes)
#define NN 50000
#define NE 800000
#define INF_ 512
#define HID 256
#define NH 8
#define HD 32
#define NCLS 40
#define NEG_SLOPE 0.2f

// ---------------- scratch (device globals; no allocs allowed) ----------------
__device__ __align__(16) float g_feat[NN * HID];
__device__ __align__(16) float g_h[NN * HID];
__device__ __align__(16) float g_feat2[NN * NCLS];
__device__ __align__(16) float g_el[NN * NH];
__device__ __align__(16) float g_er[NN * NH];
__device__ __align__(16) float g_el2[NN];
__device__ __align__(16) float g_er2[NN];
__device__ __align__(16) float g_ew[NE * NH];   // per-edge softmax numerators (CSR order)
__device__ int g_deg[NN];
__device__ int g_cursor[NN];
__device__ int g_rowptr[NN + 1];
__device__ int g_esrc[NE];
__device__ int g_edst[NE];

// ---------------- CSR build ----------------
__global__ void k_zero(int* p, int n) {
    int i = blockIdx.x * blockDim.x + threadIdx.x;
    if (i < n) p[i] = 0;
}

__global__ void k_hist(const int* __restrict__ dst, int* deg, int E) {
    int i = blockIdx.x * blockDim.x + threadIdx.x;
    if (i < E) atomicAdd(&deg[dst[i]], 1);
}

// single-block exclusive scan over 50k elements
__global__ void k_scan(const int* __restrict__ deg, int* __restrict__ rowptr, int n) {
    __shared__ int wsum[32];
    __shared__ int carry;
    int t = threadIdx.x, lane = t & 31, wid = t >> 5;
    if (t == 0) carry = 0;
    __syncthreads();
    for (int base = 0; base < n; base += blockDim.x) {
        int i = base + t;
        int v = (i < n) ? deg[i] : 0;
        int x = v;
#pragma unroll
        for (int o = 1; o < 32; o <<= 1) {
            int y = __shfl_up_sync(0xffffffffu, x, o);
            if (lane >= o) x += y;
        }
        if (lane == 31) wsum[wid] = x;
        __syncthreads();
        if (wid == 0) {
            int s = (lane < (int)(blockDim.x >> 5)) ? wsum[lane] : 0;
#pragma unroll
            for (int o = 1; o < 32; o <<= 1) {
                int y = __shfl_up_sync(0xffffffffu, s, o);
                if (lane >= o) s += y;
            }
            wsum[lane] = s;  // inclusive warp-sums scan
        }
        __syncthreads();
        int woff = (wid == 0) ? 0 : wsum[wid - 1];
        int excl = carry + woff + x - v;
        if (i < n) rowptr[i] = excl;
        int total = wsum[(blockDim.x >> 5) - 1];
        __syncthreads();
        if (t == 0) carry += total;
        __syncthreads();
    }
    if (threadIdx.x == 0) rowptr[n] = carry;
}

__global__ void k_copy(int* __restrict__ d, const int* __restrict__ s, int n) {
    int i = blockIdx.x * blockDim.x + threadIdx.x;
    if (i < n) d[i] = s[i];
}

__global__ void k_scatter(const int* __restrict__ dst, const int* __restrict__ src,
                          int* cursor, int* __restrict__ esrc, int* __restrict__ edst,
                          int E) {
    int i = blockIdx.x * blockDim.x + threadIdx.x;
    if (i < E) {
        int d = dst[i];
        int p = atomicAdd(&cursor[d], 1);
        esrc[p] = src[i];
        edst[p] = d;
    }
}

// ---------------- TF32 tensor-core GEMM: C[M,N] = A[M,K] @ B[K,N] ----------------
#define BM 128
#define BN 128
#define BK 16
#define BMP (BM + 4)
#define BNP (BN + 4)

__device__ __forceinline__ uint32_t f2tf(float f) {
    uint32_t u;
    asm("cvt.rna.tf32.f32 %0, %1;" : "=r"(u) : "f"(f));
    return u;
}

__device__ __forceinline__ void mma8(float* c, const uint32_t* a, const uint32_t* b) {
    asm volatile(
        "mma.sync.aligned.m16n8k8.row.col.f32.tf32.tf32.f32 "
        "{%0,%1,%2,%3}, {%4,%5,%6,%7}, {%8,%9}, {%0,%1,%2,%3};"
        : "+f"(c[0]), "+f"(c[1]), "+f"(c[2]), "+f"(c[3])
        : "r"(a[0]), "r"(a[1]), "r"(a[2]), "r"(a[3]), "r"(b[0]), "r"(b[1]));
}

__global__ void __launch_bounds__(256) k_mma(const float* __restrict__ A,
                                             const float* __restrict__ B,
                                             float* __restrict__ C,
                                             int M, int N, int K) {
    __shared__ uint32_t As[2][BK][BMP];
    __shared__ uint32_t Bs[2][BK][BNP];

    int tid = threadIdx.x;
    int warp = tid >> 5, lane = tid & 31;
    int gid = lane >> 2, tg = lane & 3;
    int wm = warp >> 2, wn = warp & 3;
    int m0 = blockIdx.x * BM, n0 = blockIdx.y * BN;

    int arow0 = tid >> 2, arow1 = arow0 + 64, acol = (tid & 3) * 4;
    int brow0 = tid >> 5, brow1 = brow0 + 8, bcol = (tid & 31) * 4;

    float acc[4][4][4];
#pragma unroll
    for (int mi = 0; mi < 4; mi++)
#pragma unroll
        for (int ni = 0; ni < 4; ni++)
#pragma unroll
            for (int r = 0; r < 4; r++) acc[mi][ni][r] = 0.f;

    int kTiles = K / BK;
    float4 ra0, ra1, rb0, rb1;
    const float4 z4 = make_float4(0.f, 0.f, 0.f, 0.f);

    {
        int k0 = 0;
        ra0 = (m0 + arow0 < M) ? *(const float4*)(A + (size_t)(m0 + arow0) * K + k0 + acol) : z4;
        ra1 = (m0 + arow1 < M) ? *(const float4*)(A + (size_t)(m0 + arow1) * K + k0 + acol) : z4;
        rb0 = (n0 + bcol < N) ? *(const float4*)(B + (size_t)(k0 + brow0) * N + n0 + bcol) : z4;
        rb1 = (n0 + bcol < N) ? *(const float4*)(B + (size_t)(k0 + brow1) * N + n0 + bcol) : z4;
    }
    {
        As[0][acol + 0][arow0] = f2tf(ra0.x); As[0][acol + 1][arow0] = f2tf(ra0.y);
        As[0][acol + 2][arow0] = f2tf(ra0.z); As[0][acol + 3][arow0] = f2tf(ra0.w);
        As[0][acol + 0][arow1] = f2tf(ra1.x); As[0][acol + 1][arow1] = f2tf(ra1.y);
        As[0][acol + 2][arow1] = f2tf(ra1.z); As[0][acol + 3][arow1] = f2tf(ra1.w);
        *(uint4*)&Bs[0][brow0][bcol] =
            make_uint4(f2tf(rb0.x), f2tf(rb0.y), f2tf(rb0.z), f2tf(rb0.w));
        *(uint4*)&Bs[0][brow1][bcol] =
            make_uint4(f2tf(rb1.x), f2tf(rb1.y), f2tf(rb1.z), f2tf(rb1.w));
    }
    __syncthreads();

    int buf = 0;
    for (int kt = 0; kt < kTiles; kt++) {
        if (kt + 1 < kTiles) {
            int k0 = (kt + 1) * BK;
            ra0 = (m0 + arow0 < M) ? *(const float4*)(A + (size_t)(m0 + arow0) * K + k0 + acol) : z4;
            ra1 = (m0 + arow1 < M) ? *(const float4*)(A + (size_t)(m0 + arow1) * K + k0 + acol) : z4;
            rb0 = (n0 + bcol < N) ? *(const float4*)(B + (size_t)(k0 + brow0) * N + n0 + bcol) : z4;
            rb1 = (n0 + bcol < N) ? *(const float4*)(B + (size_t)(k0 + brow1) * N + n0 + bcol) : z4;
        }
#pragma unroll
        for (int ks = 0; ks < BK; ks += 8) {
            uint32_t af[4][4], bf[4][2];
#pragma unroll
            for (int mi = 0; mi < 4; mi++) {
                int mr = wm * 64 + mi * 16 + gid;
                af[mi][0] = As[buf][ks + tg][mr];
                af[mi][1] = As[buf][ks + tg][mr + 8];
                af[mi][2] = As[buf][ks + tg + 4][mr];
                af[mi][3] = As[buf][ks + tg + 4][mr + 8];
            }
#pragma unroll
            for (int ni = 0; ni < 4; ni++) {
                int nc = wn * 32 + ni * 8 + gid;
                bf[ni][0] = Bs[buf][ks + tg][nc];
                bf[ni][1] = Bs[buf][ks + tg + 4][nc];
            }
#pragma unroll
            for (int mi = 0; mi < 4; mi++)
#pragma unroll
                for (int ni = 0; ni < 4; ni++) mma8(acc[mi][ni], af[mi], bf[ni]);
        }
        if (kt + 1 < kTiles) {
            int nb = buf ^ 1;
            As[nb][acol + 0][arow0] = f2tf(ra0.x); As[nb][acol + 1][arow0] = f2tf(ra0.y);
            As[nb][acol + 2][arow0] = f2tf(ra0.z); As[nb][acol + 3][arow0] = f2tf(ra0.w);
            As[nb][acol + 0][arow1] = f2tf(ra1.x); As[nb][acol + 1][arow1] = f2tf(ra1.y);
            As[nb][acol + 2][arow1] = f2tf(ra1.z); As[nb][acol + 3][arow1] = f2tf(ra1.w);
            *(uint4*)&Bs[nb][brow0][bcol] =
                make_uint4(f2tf(rb0.x), f2tf(rb0.y), f2tf(rb0.z), f2tf(rb0.w));
            *(uint4*)&Bs[nb][brow1][bcol] =
                make_uint4(f2tf(rb1.x), f2tf(rb1.y), f2tf(rb1.z), f2tf(rb1.w));
            __syncthreads();
            buf ^= 1;
        }
    }

#pragma unroll
    for (int mi = 0; mi < 4; mi++) {
        int r0 = m0 + wm * 64 + mi * 16 + gid;
#pragma unroll
        for (int ni = 0; ni < 4; ni++) {
            int c0 = n0 + wn * 32 + ni * 8 + tg * 2;
            if (r0 < M) {
                if (c0 < N) C[(size_t)r0 * N + c0] = acc[mi][ni][0];
                if (c0 + 1 < N) C[(size_t)r0 * N + c0 + 1] = acc[mi][ni][1];
            }
            if (r0 + 8 < M) {
                if (c0 < N) C[(size_t)(r0 + 8) * N + c0] = acc[mi][ni][2];
                if (c0 + 1 < N) C[(size_t)(r0 + 8) * N + c0 + 1] = acc[mi][ni][3];
            }
        }
    }
}

// ---------------- el/er projections ----------------
__device__ __forceinline__ float warp_sum(float v) {
#pragma unroll
    for (int o = 16; o > 0; o >>= 1) v += __shfl_xor_sync(0xffffffffu, v, o);
    return v;
}
__device__ __forceinline__ float leaky(float x) { return x > 0.f ? x : NEG_SLOPE * x; }

// one warp per node, 8 heads x 32 dims
__global__ void k_elr8(const float* __restrict__ feat, const float* __restrict__ al,
                       const float* __restrict__ ar, float* __restrict__ el,
                       float* __restrict__ er, int n) {
    int w = (blockIdx.x * blockDim.x + threadIdx.x) >> 5;
    int lane = threadIdx.x & 31;
    if (w >= n) return;
    const float* f = feat + (size_t)w * HID;
    float sl[NH], sr[NH];
#pragma unroll
    for (int j = 0; j < NH; j++) {
        float v = f[j * 32 + lane];
        sl[j] = v * __ldg(al + j * 32 + lane);
        sr[j] = v * __ldg(ar + j * 32 + lane);
    }
#pragma unroll
    for (int j = 0; j < NH; j++) { sl[j] = warp_sum(sl[j]); sr[j] = warp_sum(sr[j]); }
    if (lane == 0) {
#pragma unroll
        for (int j = 0; j < NH; j++) {
            el[w * NH + j] = sl[j];
            er[w * NH + j] = sr[j];
        }
    }
}

__global__ void k_elr1(const float* __restrict__ feat2, const float* __restrict__ al,
                       const float* __restrict__ ar, float* __restrict__ el,
                       float* __restrict__ er, int n) {
    int w = (blockIdx.x * blockDim.x + threadIdx.x) >> 5;
    int lane = threadIdx.x & 31;
    if (w >= n) return;
    const float* f = feat2 + (size_t)w * NCLS;
    float sl = f[lane] * __ldg(al + lane);
    float sr = f[lane] * __ldg(ar + lane);
    if (lane < 8) {
        sl += f[32 + lane] * __ldg(al + 32 + lane);
        sr += f[32 + lane] * __ldg(ar + 32 + lane);
    }
    sl = warp_sum(sl);
    sr = warp_sum(sr);
    if (lane == 0) { el[w] = sl; er[w] = sr; }
}

// ---------------- edge weights (lane-parallel exp) ----------------
// one thread per edge (CSR order): w[j] = exp(leaky(el[src][j] + er[dst][j]))
__global__ void k_w8(const float* __restrict__ el, const float* __restrict__ er,
                     const int* __restrict__ esrc, const int* __restrict__ edst,
                     float* __restrict__ ew, int E) {
    int i = blockIdx.x * blockDim.x + threadIdx.x;
    if (i >= E) return;
    int s = esrc[i], d = edst[i];
    float4 l0 = *(const float4*)(el + s * NH);
    float4 l1 = *(const float4*)(el + s * NH + 4);
    float4 r0 = *(const float4*)(er + d * NH);
    float4 r1 = *(const float4*)(er + d * NH + 4);
    float4 w0, w1;
    w0.x = __expf(leaky(l0.x + r0.x));
    w0.y = __expf(leaky(l0.y + r0.y));
    w0.z = __expf(leaky(l0.z + r0.z));
    w0.w = __expf(leaky(l0.w + r0.w));
    w1.x = __expf(leaky(l1.x + r1.x));
    w1.y = __expf(leaky(l1.y + r1.y));
    w1.z = __expf(leaky(l1.z + r1.z));
    w1.w = __expf(leaky(l1.w + r1.w));
    *(float4*)(ew + (size_t)i * NH) = w0;
    *(float4*)(ew + (size_t)i * NH + 4) = w1;
}

__global__ void k_w1(const float* __restrict__ el, const float* __restrict__ er,
                     const int* __restrict__ esrc, const int* __restrict__ edst,
                     float* __restrict__ ew, int E) {
    int i = blockIdx.x * blockDim.x + threadIdx.x;
    if (i >= E) return;
    ew[i] = __expf(leaky(el[esrc[i]] + er[edst[i]]));
}

// ---------------- aggregation: one warp per dst node, single pass ----------------
// lane l owns 8 contiguous feature columns [l*8, l*8+8); its head is l>>2.
__global__ void k_agg8(const float* __restrict__ feat, const float* __restrict__ ew,
                       const int* __restrict__ rowptr, const int* __restrict__ esrc,
                       const float* __restrict__ bias, float* __restrict__ out,
                       int n, int do_relu) {
    int node = (blockIdx.x * blockDim.x + threadIdx.x) >> 5;
    int lane = threadIdx.x & 31;
    if (node >= n) return;
    int beg = rowptr[node], end = rowptr[node + 1];
    int head = lane >> 2;
    int col = lane * 8;

    float4 acc0 = make_float4(0.f, 0.f, 0.f, 0.f);
    float4 acc1 = acc0;
    float den = 0.f;

#pragma unroll 2
    for (int i = beg; i < end; i++) {
        int s = esrc[i];  // warp-uniform
        float w = ew[(size_t)i * NH + head];
        den += w;
        const float4* fp = (const float4*)(feat + (size_t)s * HID + col);
        float4 f0 = fp[0], f1 = fp[1];
        acc0.x = fmaf(w, f0.x, acc0.x); acc0.y = fmaf(w, f0.y, acc0.y);
        acc0.z = fmaf(w, f0.z, acc0.z); acc0.w = fmaf(w, f0.w, acc0.w);
        acc1.x = fmaf(w, f1.x, acc1.x); acc1.y = fmaf(w, f1.y, acc1.y);
        acc1.z = fmaf(w, f1.z, acc1.z); acc1.w = fmaf(w, f1.w, acc1.w);
    }
    float inv = 1.f / fmaxf(den, 1e-9f);
    float4 b0 = *(const float4*)(bias + col);
    float4 b1 = *(const float4*)(bias + col + 4);
    float4 o0, o1;
    o0.x = fmaf(acc0.x, inv, b0.x); o0.y = fmaf(acc0.y, inv, b0.y);
    o0.z = fmaf(acc0.z, inv, b0.z); o0.w = fmaf(acc0.w, inv, b0.w);
    o1.x = fmaf(acc1.x, inv, b1.x); o1.y = fmaf(acc1.y, inv, b1.y);
    o1.z = fmaf(acc1.z, inv, b1.z); o1.w = fmaf(acc1.w, inv, b1.w);
    if (do_relu) {
        o0.x = fmaxf(o0.x, 0.f); o0.y = fmaxf(o0.y, 0.f);
        o0.z = fmaxf(o0.z, 0.f); o0.w = fmaxf(o0.w, 0.f);
        o1.x = fmaxf(o1.x, 0.f); o1.y = fmaxf(o1.y, 0.f);
        o1.z = fmaxf(o1.z, 0.f); o1.w = fmaxf(o1.w, 0.f);
    }
    float* op = out + (size_t)node * HID + col;
    *(float4*)op = o0;
    *(float4*)(op + 4) = o1;
}

// output layer: 1 head, 40 dims; lane<10 owns float4 cols [lane*4, lane*4+4)
__global__ void k_agg1(const float* __restrict__ feat2, const float* __restrict__ ew,
                       const int* __restrict__ rowptr, const int* __restrict__ esrc,
                       const float* __restrict__ bias, float* __restrict__ out, int n) {
    int node = (blockIdx.x * blockDim.x + threadIdx.x) >> 5;
    int lane = threadIdx.x & 31;
    if (node >= n) return;
    int beg = rowptr[node], end = rowptr[node + 1];

    float4 acc = make_float4(0.f, 0.f, 0.f, 0.f);
    float den = 0.f;
#pragma unroll 2
    for (int i = beg; i < end; i++) {
        int s = esrc[i];
        float w = ew[i];
        den += w;
        if (lane < 10) {
            float4 f = *(const float4*)(feat2 + (size_t)s * NCLS + lane * 4);
            acc.x = fmaf(w, f.x, acc.x); acc.y = fmaf(w, f.y, acc.y);
            acc.z = fmaf(w, f.z, acc.z); acc.w = fmaf(w, f.w, acc.w);
        }
    }
    float inv = 1.f / fmaxf(den, 1e-9f);
    if (lane < 10) {
        float4 b = *(const float4*)(bias + lane * 4);
        float4 o;
        o.x = fmaf(acc.x, inv, b.x); o.y = fmaf(acc.y, inv, b.y);
        o.z = fmaf(acc.z, inv, b.z); o.w = fmaf(acc.w, inv, b.w);
        *(float4*)(out + (size_t)node * NCLS + lane * 4) = o;
    }
}

// ---------------- host ----------------
extern "C" void kernel_launch(void* const* d_in, const int* in_sizes, int n_in,
                              void* d_out, int out_size) {
    const float* in_feat = (const float*)d_in[0];
    const int*   src     = (const int*)d_in[1];
    const int*   dst     = (const int*)d_in[2];
    const float* W0  = (const float*)d_in[3];
    const float* al0 = (const float*)d_in[4];
    const float* ar0 = (const float*)d_in[5];
    const float* b0  = (const float*)d_in[6];
    const float* W1  = (const float*)d_in[7];
    const float* al1 = (const float*)d_in[8];
    const float* ar1 = (const float*)d_in[9];
    const float* b1  = (const float*)d_in[10];
    const float* W2  = (const float*)d_in[11];
    const float* al2 = (const float*)d_in[12];
    const float* ar2 = (const float*)d_in[13];
    const float* b2  = (const float*)d_in[14];
    float* out = (float*)d_out;

    int n = NN;
    int E = in_sizes[1];

    float *feat, *h, *feat2, *el, *er, *el2, *er2, *ew;
    int *deg, *cur, *rp, *esrc, *edst;
    cudaGetSymbolAddress((void**)&feat, g_feat);
    cudaGetSymbolAddress((void**)&h, g_h);
    cudaGetSymbolAddress((void**)&feat2, g_feat2);
    cudaGetSymbolAddress((void**)&el, g_el);
    cudaGetSymbolAddress((void**)&er, g_er);
    cudaGetSymbolAddress((void**)&el2, g_el2);
    cudaGetSymbolAddress((void**)&er2, g_er2);
    cudaGetSymbolAddress((void**)&ew, g_ew);
    cudaGetSymbolAddress((void**)&deg, g_deg);
    cudaGetSymbolAddress((void**)&cur, g_cursor);
    cudaGetSymbolAddress((void**)&rp, g_rowptr);
    cudaGetSymbolAddress((void**)&esrc, g_esrc);
    cudaGetSymbolAddress((void**)&edst, g_edst);

    // CSR by dst (edge structure constant across layers)
    k_zero<<<(n + 255) / 256, 256>>>(deg, n);
    k_hist<<<(E + 255) / 256, 256>>>(dst, deg, E);
    k_scan<<<1, 1024>>>(deg, rp, n);
    k_copy<<<(n + 255) / 256, 256>>>(cur, rp, n);
    k_scatter<<<(E + 255) / 256, 256>>>(dst, src, cur, esrc, edst, E);

    int nwarp_blocks = (n + 7) / 8;
    int eblocks = (E + 255) / 256;

    // layer 0
    {
        dim3 g((n + BM - 1) / BM, (HID + BN - 1) / BN);
        k_mma<<<g, 256>>>(in_feat, W0, feat, n, HID, INF_);
        k_elr8<<<nwarp_blocks, 256>>>(feat, al0, ar0, el, er, n);
        k_w8<<<eblocks, 256>>>(el, er, esrc, edst, ew, E);
        k_agg8<<<nwarp_blocks, 256>>>(feat, ew, rp, esrc, b0, h, n, 1);
    }
    // layer 1
    {
        dim3 g((n + BM - 1) / BM, (HID + BN - 1) / BN);
        k_mma<<<g, 256>>>(h, W1, feat, n, HID, HID);
        k_elr8<<<nwarp_blocks, 256>>>(feat, al1, ar1, el, er, n);
        k_w8<<<eblocks, 256>>>(el, er, esrc, edst, ew, E);
        k_agg8<<<nwarp_blocks, 256>>>(feat, ew, rp, esrc, b1, h, n, 1);
    }
    // output layer (1 head, 40 classes)
    {
        dim3 g((n + BM - 1) / BM, (NCLS + BN - 1) / BN);
        k_mma<<<g, 256>>>(h, W2, feat2, n, NCLS, HID);
        k_elr1<<<nwarp_blocks, 256>>>(feat2, al2, ar2, el2, er2, n);
        k_w1<<<eblocks, 256>>>(el2, er2, esrc, edst, ew, E);
        k_agg1<<<nwarp_blocks, 256>>>(feat2, ew, rp, esrc, b2, out, n);
    }
}

// round 7
// speedup vs baseline: 1.7826x; 1.0583x over previous
#include <cuda_runtime.h>
#include <float.h>
#include <stdint.h>

// Problem constants (fixed shapes)
#define NN 50000
#define NE 800000
#define INF_ 512
#define HID 256
#define NH 8
#define HD 32
#define NCLS 40
#define NEG_SLOPE 0.2f

// ---------------- scratch (device globals; no allocs allowed) ----------------
__device__ __align__(16) float g_feat[NN * HID];
__device__ __align__(16) float g_h[NN * HID];
__device__ __align__(16) float g_feat2[NN * NCLS];
__device__ __align__(16) float g_el[NN * NH];
__device__ __align__(16) float g_er[NN * NH];
__device__ __align__(16) float g_el2[NN];
__device__ __align__(16) float g_er2[NN];
__device__ __align__(16) float g_ew[NE * NH];      // per-edge softmax numerators
__device__ __align__(16) float g_a0[NN * INF_];    // tf32-rounded in_feat
__device__ __align__(16) float g_w0[INF_ * HID];   // tf32-rounded weights
__device__ __align__(16) float g_w1[HID * HID];
__device__ __align__(16) float g_w2[HID * NCLS];
__device__ int g_deg[NN];
__device__ int g_cursor[NN];
__device__ int g_rowptr[NN + 1];
__device__ int g_esrc[NE];
__device__ int g_edst[NE];

// ---------------- CSR build ----------------
__global__ void k_zero(int* p, int n) {
    int i = blockIdx.x * blockDim.x + threadIdx.x;
    if (i < n) p[i] = 0;
}

__global__ void k_hist(const int* __restrict__ dst, int* deg, int E) {
    int i = blockIdx.x * blockDim.x + threadIdx.x;
    if (i < E) atomicAdd(&deg[dst[i]], 1);
}

__global__ void k_scan(const int* __restrict__ deg, int* __restrict__ rowptr, int n) {
    __shared__ int wsum[32];
    __shared__ int carry;
    int t = threadIdx.x, lane = t & 31, wid = t >> 5;
    if (t == 0) carry = 0;
    __syncthreads();
    for (int base = 0; base < n; base += blockDim.x) {
        int i = base + t;
        int v = (i < n) ? deg[i] : 0;
        int x = v;
#pragma unroll
        for (int o = 1; o < 32; o <<= 1) {
            int y = __shfl_up_sync(0xffffffffu, x, o);
            if (lane >= o) x += y;
        }
        if (lane == 31) wsum[wid] = x;
        __syncthreads();
        if (wid == 0) {
            int s = (lane < (int)(blockDim.x >> 5)) ? wsum[lane] : 0;
#pragma unroll
            for (int o = 1; o < 32; o <<= 1) {
                int y = __shfl_up_sync(0xffffffffu, s, o);
                if (lane >= o) s += y;
            }
            wsum[lane] = s;
        }
        __syncthreads();
        int woff = (wid == 0) ? 0 : wsum[wid - 1];
        int excl = carry + woff + x - v;
        if (i < n) rowptr[i] = excl;
        int total = wsum[(blockDim.x >> 5) - 1];
        __syncthreads();
        if (t == 0) carry += total;
        __syncthreads();
    }
    if (threadIdx.x == 0) rowptr[n] = carry;
}

__global__ void k_copy(int* __restrict__ d, const int* __restrict__ s, int n) {
    int i = blockIdx.x * blockDim.x + threadIdx.x;
    if (i < n) d[i] = s[i];
}

__global__ void k_scatter(const int* __restrict__ dst, const int* __restrict__ src,
                          int* cursor, int* __restrict__ esrc, int* __restrict__ edst,
                          int E) {
    int i = blockIdx.x * blockDim.x + threadIdx.x;
    if (i < E) {
        int d = dst[i];
        int p = atomicAdd(&cursor[d], 1);
        esrc[p] = src[i];
        edst[p] = d;
    }
}

// ---------------- tf32 pre-round (elementwise, vectorized) ----------------
__device__ __forceinline__ uint32_t f2tf(float f) {
    uint32_t u;
    asm("cvt.rna.tf32.f32 %0, %1;" : "=r"(u) : "f"(f));
    return u;
}
__device__ __forceinline__ float f2tff(float f) { return __uint_as_float(f2tf(f)); }

__global__ void k_cvt(float* __restrict__ dst, const float* __restrict__ src, int n4) {
    int i = blockIdx.x * blockDim.x + threadIdx.x;
    if (i >= n4) return;
    float4 v = ((const float4*)src)[i];
    v.x = f2tff(v.x); v.y = f2tff(v.y); v.z = f2tff(v.z); v.w = f2tff(v.w);
    ((float4*)dst)[i] = v;
}

// ---------------- TF32 tensor-core GEMM, cp.async 4-stage pipeline ----------------
// Inputs MUST already be tf32-rounded fp32. C[M,N] = A[M,K] @ B[K,N].
#define BM 128
#define BN 128
#define BK 16
#define NSTAGE 4
#define A_STRIDE 20            // words per A row (pad 16 -> 20: conflict-free frags)
#define B_STRIDE 136           // words per B row (pad 128 -> 136)
#define A_STAGE_W (BM * A_STRIDE)       // 2560 words
#define B_STAGE_W (BK * B_STRIDE)       // 2176 words
#define SMEM_BYTES ((NSTAGE * (A_STAGE_W + B_STAGE_W)) * 4)  // 75776

__device__ __forceinline__ void mma8(float* c, const uint32_t* a, const uint32_t* b) {
    asm volatile(
        "mma.sync.aligned.m16n8k8.row.col.f32.tf32.tf32.f32 "
        "{%0,%1,%2,%3}, {%4,%5,%6,%7}, {%8,%9}, {%0,%1,%2,%3};"
        : "+f"(c[0]), "+f"(c[1]), "+f"(c[2]), "+f"(c[3])
        : "r"(a[0]), "r"(a[1]), "r"(a[2]), "r"(a[3]), "r"(b[0]), "r"(b[1]));
}

__device__ __forceinline__ void cp16(uint32_t dst, const void* src, bool pred) {
    int sz = pred ? 16 : 0;
    asm volatile("cp.async.cg.shared.global [%0], [%1], 16, %2;"
                 :: "r"(dst), "l"(src), "r"(sz));
}
__device__ __forceinline__ void cp_commit() {
    asm volatile("cp.async.commit_group;");
}
template <int N>
__device__ __forceinline__ void cp_wait() {
    asm volatile("cp.async.wait_group %0;" :: "n"(N));
}

__global__ void __launch_bounds__(256) k_mma(const float* __restrict__ A,
                                             const float* __restrict__ B,
                                             float* __restrict__ C,
                                             int M, int N, int K) {
    extern __shared__ float smem[];
    uint32_t sbase;
    asm("{ .reg .u64 t; cvta.to.shared.u64 t, %1; cvt.u32.u64 %0, t; }"
        : "=r"(sbase) : "l"(smem));

    int tid = threadIdx.x;
    int warp = tid >> 5, lane = tid & 31;
    int gid = lane >> 2, tg = lane & 3;
    int wm = warp >> 2, wn = warp & 3;
    int m0 = blockIdx.x * BM, n0 = blockIdx.y * BN;

    // fill decomposition: thread covers 2 A chunks + 2 B chunks of 16B
    int ar0 = tid >> 2, ar1 = ar0 + 64;             // A rows
    int akc = (tid & 3) * 4;                        // A k-col (floats)
    int bk0 = tid >> 5, bk1 = bk0 + 8;              // B k-rows
    int bnc = (tid & 31) * 4;                       // B n-col (floats)
    bool bok = (n0 + bnc + 4 <= N);

    float acc[4][4][4];
#pragma unroll
    for (int mi = 0; mi < 4; mi++)
#pragma unroll
        for (int ni = 0; ni < 4; ni++)
#pragma unroll
            for (int r = 0; r < 4; r++) acc[mi][ni][r] = 0.f;

    int kTiles = K / BK;

#define FILL_STAGE(s, kt)                                                             \
    do {                                                                              \
        int k0 = (kt) * BK;                                                           \
        uint32_t abase = sbase + (uint32_t)(s) * (A_STAGE_W * 4);                     \
        uint32_t bbase = sbase + (uint32_t)(NSTAGE * A_STAGE_W + (s) * B_STAGE_W) * 4;\
        cp16(abase + (ar0 * A_STRIDE + akc) * 4,                                      \
             A + (size_t)(m0 + ar0) * K + k0 + akc, m0 + ar0 < M);                    \
        cp16(abase + (ar1 * A_STRIDE + akc) * 4,                                      \
             A + (size_t)(m0 + ar1) * K + k0 + akc, m0 + ar1 < M);                    \
        cp16(bbase + (bk0 * B_STRIDE + bnc) * 4,                                      \
             B + (size_t)(k0 + bk0) * N + n0 + bnc, bok);                             \
        cp16(bbase + (bk1 * B_STRIDE + bnc) * 4,                                      \
             B + (size_t)(k0 + bk1) * N + n0 + bnc, bok);                             \
    } while (0)

    // prologue: stages 0..NSTAGE-2
#pragma unroll
    for (int s = 0; s < NSTAGE - 1; s++) {
        if (s < kTiles) FILL_STAGE(s, s);
        cp_commit();
    }

    const uint32_t* As = (const uint32_t*)smem;
    const uint32_t* Bs = (const uint32_t*)smem + NSTAGE * A_STAGE_W;

    for (int kt = 0; kt < kTiles; kt++) {
        cp_wait<NSTAGE - 2>();
        __syncthreads();

        int nkt = kt + NSTAGE - 1;
        if (nkt < kTiles) FILL_STAGE(nkt % NSTAGE, nkt);
        cp_commit();

        int buf = kt % NSTAGE;
        const uint32_t* Ab = As + buf * A_STAGE_W;
        const uint32_t* Bb = Bs + buf * B_STAGE_W;
#pragma unroll
        for (int ks = 0; ks < BK; ks += 8) {
            uint32_t af[4][4], bf[4][2];
#pragma unroll
            for (int mi = 0; mi < 4; mi++) {
                int mr = wm * 64 + mi * 16 + gid;
                af[mi][0] = Ab[mr * A_STRIDE + ks + tg];
                af[mi][1] = Ab[(mr + 8) * A_STRIDE + ks + tg];
                af[mi][2] = Ab[mr * A_STRIDE + ks + tg + 4];
                af[mi][3] = Ab[(mr + 8) * A_STRIDE + ks + tg + 4];
            }
#pragma unroll
            for (int ni = 0; ni < 4; ni++) {
                int nc = wn * 32 + ni * 8 + gid;
                bf[ni][0] = Bb[(ks + tg) * B_STRIDE + nc];
                bf[ni][1] = Bb[(ks + tg + 4) * B_STRIDE + nc];
            }
#pragma unroll
            for (int mi = 0; mi < 4; mi++)
#pragma unroll
                for (int ni = 0; ni < 4; ni++) mma8(acc[mi][ni], af[mi], bf[ni]);
        }
        __syncthreads();
    }

    // epilogue
#pragma unroll
    for (int mi = 0; mi < 4; mi++) {
        int r0 = m0 + wm * 64 + mi * 16 + gid;
#pragma unroll
        for (int ni = 0; ni < 4; ni++) {
            int c0 = n0 + wn * 32 + ni * 8 + tg * 2;
            if (r0 < M) {
                if (c0 < N) C[(size_t)r0 * N + c0] = acc[mi][ni][0];
                if (c0 + 1 < N) C[(size_t)r0 * N + c0 + 1] = acc[mi][ni][1];
            }
            if (r0 + 8 < M) {
                if (c0 < N) C[(size_t)(r0 + 8) * N + c0] = acc[mi][ni][2];
                if (c0 + 1 < N) C[(size_t)(r0 + 8) * N + c0 + 1] = acc[mi][ni][3];
            }
        }
    }
}

// ---------------- el/er projections ----------------
__device__ __forceinline__ float warp_sum(float v) {
#pragma unroll
    for (int o = 16; o > 0; o >>= 1) v += __shfl_xor_sync(0xffffffffu, v, o);
    return v;
}
__device__ __forceinline__ float leaky(float x) { return x > 0.f ? x : NEG_SLOPE * x; }

__global__ void k_elr8(const float* __restrict__ feat, const float* __restrict__ al,
                       const float* __restrict__ ar, float* __restrict__ el,
                       float* __restrict__ er, int n) {
    int w = (blockIdx.x * blockDim.x + threadIdx.x) >> 5;
    int lane = threadIdx.x & 31;
    if (w >= n) return;
    const float* f = feat + (size_t)w * HID;
    float sl[NH], sr[NH];
#pragma unroll
    for (int j = 0; j < NH; j++) {
        float v = f[j * 32 + lane];
        sl[j] = v * __ldg(al + j * 32 + lane);
        sr[j] = v * __ldg(ar + j * 32 + lane);
    }
#pragma unroll
    for (int j = 0; j < NH; j++) { sl[j] = warp_sum(sl[j]); sr[j] = warp_sum(sr[j]); }
    if (lane == 0) {
#pragma unroll
        for (int j = 0; j < NH; j++) {
            el[w * NH + j] = sl[j];
            er[w * NH + j] = sr[j];
        }
    }
}

__global__ void k_elr1(const float* __restrict__ feat2, const float* __restrict__ al,
                       const float* __restrict__ ar, float* __restrict__ el,
                       float* __restrict__ er, int n) {
    int w = (blockIdx.x * blockDim.x + threadIdx.x) >> 5;
    int lane = threadIdx.x & 31;
    if (w >= n) return;
    const float* f = feat2 + (size_t)w * NCLS;
    float sl = f[lane] * __ldg(al + lane);
    float sr = f[lane] * __ldg(ar + lane);
    if (lane < 8) {
        sl += f[32 + lane] * __ldg(al + 32 + lane);
        sr += f[32 + lane] * __ldg(ar + 32 + lane);
    }
    sl = warp_sum(sl);
    sr = warp_sum(sr);
    if (lane == 0) { el[w] = sl; er[w] = sr; }
}

// ---------------- edge weights (lane-parallel exp) ----------------
__global__ void k_w8(const float* __restrict__ el, const float* __restrict__ er,
                     const int* __restrict__ esrc, const int* __restrict__ edst,
                     float* __restrict__ ew, int E) {
    int i = blockIdx.x * blockDim.x + threadIdx.x;
    if (i >= E) return;
    int s = esrc[i], d = edst[i];
    float4 l0 = *(const float4*)(el + s * NH);
    float4 l1 = *(const float4*)(el + s * NH + 4);
    float4 r0 = *(const float4*)(er + d * NH);
    float4 r1 = *(const float4*)(er + d * NH + 4);
    float4 w0, w1;
    w0.x = __expf(leaky(l0.x + r0.x));
    w0.y = __expf(leaky(l0.y + r0.y));
    w0.z = __expf(leaky(l0.z + r0.z));
    w0.w = __expf(leaky(l0.w + r0.w));
    w1.x = __expf(leaky(l1.x + r1.x));
    w1.y = __expf(leaky(l1.y + r1.y));
    w1.z = __expf(leaky(l1.z + r1.z));
    w1.w = __expf(leaky(l1.w + r1.w));
    *(float4*)(ew + (size_t)i * NH) = w0;
    *(float4*)(ew + (size_t)i * NH + 4) = w1;
}

__global__ void k_w1(const float* __restrict__ el, const float* __restrict__ er,
                     const int* __restrict__ esrc, const int* __restrict__ edst,
                     float* __restrict__ ew, int E) {
    int i = blockIdx.x * blockDim.x + threadIdx.x;
    if (i >= E) return;
    ew[i] = __expf(leaky(el[esrc[i]] + er[edst[i]]));
}

// ---------------- aggregation: one warp per dst node, single pass ----------------
// lane owns contiguous cols [lane*4, lane*4+4) (head lane>>3) and
// [128+lane*4, 128+lane*4+4) (head 4+(lane>>3)): two contiguous 512B gathers.
// Output h feeds the next GEMM, so it is rounded to tf32 here (numerically
// identical to rounding inside the GEMM).
__global__ void k_agg8(const float* __restrict__ feat, const float* __restrict__ ew,
                       const int* __restrict__ rowptr, const int* __restrict__ esrc,
                       const float* __restrict__ bias, float* __restrict__ out,
                       int n, int do_relu) {
    int node = (blockIdx.x * blockDim.x + threadIdx.x) >> 5;
    int lane = threadIdx.x & 31;
    if (node >= n) return;
    int beg = rowptr[node], end = rowptr[node + 1];
    int h0 = lane >> 3, h1 = 4 + h0;
    int col = lane * 4;

    float4 acc0 = make_float4(0.f, 0.f, 0.f, 0.f);
    float4 acc1 = acc0;
    float den0 = 0.f, den1 = 0.f;

#pragma unroll 4
    for (int i = beg; i < end; i++) {
        int s = esrc[i];  // warp-uniform
        float w0 = ew[(size_t)i * NH + h0];
        float w1 = ew[(size_t)i * NH + h1];
        den0 += w0; den1 += w1;
        const float* fp = feat + (size_t)s * HID;
        float4 f0 = *(const float4*)(fp + col);
        float4 f1 = *(const float4*)(fp + 128 + col);
        acc0.x = fmaf(w0, f0.x, acc0.x); acc0.y = fmaf(w0, f0.y, acc0.y);
        acc0.z = fmaf(w0, f0.z, acc0.z); acc0.w = fmaf(w0, f0.w, acc0.w);
        acc1.x = fmaf(w1, f1.x, acc1.x); acc1.y = fmaf(w1, f1.y, acc1.y);
        acc1.z = fmaf(w1, f1.z, acc1.z); acc1.w = fmaf(w1, f1.w, acc1.w);
    }
    float inv0 = 1.f / fmaxf(den0, 1e-9f);
    float inv1 = 1.f / fmaxf(den1, 1e-9f);
    float4 b0 = *(const float4*)(bias + col);
    float4 b1 = *(const float4*)(bias + 128 + col);
    float4 o0, o1;
    o0.x = fmaf(acc0.x, inv0, b0.x); o0.y = fmaf(acc0.y, inv0, b0.y);
    o0.z = fmaf(acc0.z, inv0, b0.z); o0.w = fmaf(acc0.w, inv0, b0.w);
    o1.x = fmaf(acc1.x, inv1, b1.x); o1.y = fmaf(acc1.y, inv1, b1.y);
    o1.z = fmaf(acc1.z, inv1, b1.z); o1.w = fmaf(acc1.w, inv1, b1.w);
    if (do_relu) {
        o0.x = fmaxf(o0.x, 0.f); o0.y = fmaxf(o0.y, 0.f);
        o0.z = fmaxf(o0.z, 0.f); o0.w = fmaxf(o0.w, 0.f);
        o1.x = fmaxf(o1.x, 0.f); o1.y = fmaxf(o1.y, 0.f);
        o1.z = fmaxf(o1.z, 0.f); o1.w = fmaxf(o1.w, 0.f);
    }
    // round to tf32 for the consuming GEMM
    o0.x = f2tff(o0.x); o0.y = f2tff(o0.y); o0.z = f2tff(o0.z); o0.w = f2tff(o0.w);
    o1.x = f2tff(o1.x); o1.y = f2tff(o1.y); o1.z = f2tff(o1.z); o1.w = f2tff(o1.w);
    float* op = out + (size_t)node * HID;
    *(float4*)(op + col) = o0;
    *(float4*)(op + 128 + col) = o1;
}

// output layer: 1 head, 40 dims; lane<10 owns float4 cols [lane*4, lane*4+4)
__global__ void k_agg1(const float* __restrict__ feat2, const float* __restrict__ ew,
                       const int* __restrict__ rowptr, const int* __restrict__ esrc,
                       const float* __restrict__ bias, float* __restrict__ out, int n) {
    int node = (blockIdx.x * blockDim.x + threadIdx.x) >> 5;
    int lane = threadIdx.x & 31;
    if (node >= n) return;
    int beg = rowptr[node], end = rowptr[node + 1];

    float4 acc = make_float4(0.f, 0.f, 0.f, 0.f);
    float den = 0.f;
#pragma unroll 4
    for (int i = beg; i < end; i++) {
        int s = esrc[i];
        float w = ew[i];
        den += w;
        if (lane < 10) {
            float4 f = *(const float4*)(feat2 + (size_t)s * NCLS + lane * 4);
            acc.x = fmaf(w, f.x, acc.x); acc.y = fmaf(w, f.y, acc.y);
            acc.z = fmaf(w, f.z, acc.z); acc.w = fmaf(w, f.w, acc.w);
        }
    }
    float inv = 1.f / fmaxf(den, 1e-9f);
    if (lane < 10) {
        float4 b = *(const float4*)(bias + lane * 4);
        float4 o;
        o.x = fmaf(acc.x, inv, b.x); o.y = fmaf(acc.y, inv, b.y);
        o.z = fmaf(acc.z, inv, b.z); o.w = fmaf(acc.w, inv, b.w);
        *(float4*)(out + (size_t)node * NCLS + lane * 4) = o;
    }
}

// ---------------- host ----------------
extern "C" void kernel_launch(void* const* d_in, const int* in_sizes, int n_in,
                              void* d_out, int out_size) {
    const float* in_feat = (const float*)d_in[0];
    const int*   src     = (const int*)d_in[1];
    const int*   dst     = (const int*)d_in[2];
    const float* W0  = (const float*)d_in[3];
    const float* al0 = (const float*)d_in[4];
    const float* ar0 = (const float*)d_in[5];
    const float* b0  = (const float*)d_in[6];
    const float* W1  = (const float*)d_in[7];
    const float* al1 = (const float*)d_in[8];
    const float* ar1 = (const float*)d_in[9];
    const float* b1  = (const float*)d_in[10];
    const float* W2  = (const float*)d_in[11];
    const float* al2 = (const float*)d_in[12];
    const float* ar2 = (const float*)d_in[13];
    const float* b2  = (const float*)d_in[14];
    float* out = (float*)d_out;

    int n = NN;
    int E = in_sizes[1];

    float *feat, *h, *feat2, *el, *er, *el2, *er2, *ew, *a0, *w0, *w1, *w2;
    int *deg, *cur, *rp, *esrc, *edst;
    cudaGetSymbolAddress((void**)&feat, g_feat);
    cudaGetSymbolAddress((void**)&h, g_h);
    cudaGetSymbolAddress((void**)&feat2, g_feat2);
    cudaGetSymbolAddress((void**)&el, g_el);
    cudaGetSymbolAddress((void**)&er, g_er);
    cudaGetSymbolAddress((void**)&el2, g_el2);
    cudaGetSymbolAddress((void**)&er2, g_er2);
    cudaGetSymbolAddress((void**)&ew, g_ew);
    cudaGetSymbolAddress((void**)&a0, g_a0);
    cudaGetSymbolAddress((void**)&w0, g_w0);
    cudaGetSymbolAddress((void**)&w1, g_w1);
    cudaGetSymbolAddress((void**)&w2, g_w2);
    cudaGetSymbolAddress((void**)&deg, g_deg);
    cudaGetSymbolAddress((void**)&cur, g_cursor);
    cudaGetSymbolAddress((void**)&rp, g_rowptr);
    cudaGetSymbolAddress((void**)&esrc, g_esrc);
    cudaGetSymbolAddress((void**)&edst, g_edst);

    static int attr_done = 0;
    if (!attr_done) {
        cudaFuncSetAttribute(k_mma, cudaFuncAttributeMaxDynamicSharedMemorySize,
                             SMEM_BYTES);
        attr_done = 1;
    }

    // CSR by dst
    k_zero<<<(n + 255) / 256, 256>>>(deg, n);
    k_hist<<<(E + 255) / 256, 256>>>(dst, deg, E);
    k_scan<<<1, 1024>>>(deg, rp, n);
    k_copy<<<(n + 255) / 256, 256>>>(cur, rp, n);
    k_scatter<<<(E + 255) / 256, 256>>>(dst, src, cur, esrc, edst, E);

    // pre-round GEMM inputs to tf32 (bit-identical to rounding inside GEMM)
    k_cvt<<<(NN * INF_ / 4 + 255) / 256, 256>>>(a0, in_feat, NN * INF_ / 4);
    k_cvt<<<(INF_ * HID / 4 + 255) / 256, 256>>>(w0, W0, INF_ * HID / 4);
    k_cvt<<<(HID * HID / 4 + 255) / 256, 256>>>(w1, W1, HID * HID / 4);
    k_cvt<<<(HID * NCLS / 4 + 255) / 256, 256>>>(w2, W2, HID * NCLS / 4);

    int nwarp_blocks = (n + 7) / 8;
    int eblocks = (E + 255) / 256;

    // layer 0
    {
        dim3 g((n + BM - 1) / BM, (HID + BN - 1) / BN);
        k_mma<<<g, 256, SMEM_BYTES>>>(a0, w0, feat, n, HID, INF_);
        k_elr8<<<nwarp_blocks, 256>>>(feat, al0, ar0, el, er, n);
        k_w8<<<eblocks, 256>>>(el, er, esrc, edst, ew, E);
        k_agg8<<<nwarp_blocks, 256>>>(feat, ew, rp, esrc, b0, h, n, 1);
    }
    // layer 1 (h already tf32-rounded by k_agg8)
    {
        dim3 g((n + BM - 1) / BM, (HID + BN - 1) / BN);
        k_mma<<<g, 256, SMEM_BYTES>>>(h, w1, feat, n, HID, HID);
        k_elr8<<<nwarp_blocks, 256>>>(feat, al1, ar1, el, er, n);
        k_w8<<<eblocks, 256>>>(el, er, esrc, edst, ew, E);
        k_agg8<<<nwarp_blocks, 256>>>(feat, ew, rp, esrc, b1, h, n, 1);
    }
    // output layer (1 head, 40 classes)
    {
        dim3 g((n + BM - 1) / BM, (NCLS + BN - 1) / BN);
        k_mma<<<g, 256, SMEM_BYTES>>>(h, w2, feat2, n, NCLS, HID);
        k_elr1<<<nwarp_blocks, 256>>>(feat2, al2, ar2, el2, er2, n);
        k_w1<<<eblocks, 256>>>(el2, er2, esrc, edst, ew, E);
        k_agg1<<<nwarp_blocks, 256>>>(feat2, ew, rp, esrc, b2, out, n);
    }
}

// round 9
// speedup vs baseline: 2.0007x; 1.1223x over previous
#include <cuda_runtime.h>
#include <cuda_fp16.h>
#include <float.h>
#include <stdint.h>

// Problem constants (fixed shapes)
#define NN 50000
#define NE 800000
#define INF_ 512
#define HID 256
#define NH 8
#define HD 32
#define NCLS 40
#define NEG_SLOPE 0.2f

// ---------------- scratch (device globals; no allocs allowed) ----------------
__device__ __align__(16) float g_feat[NN * HID];
__device__ __align__(16) __half g_feath[NN * HID];   // fp16 copy for edge gather
__device__ __align__(16) float g_h[NN * HID];
__device__ __align__(16) float g_feat2[NN * NCLS];
__device__ __align__(16) float g_el[NN * NH];
__device__ __align__(16) float g_er[NN * NH];
__device__ __align__(16) float g_el2[NN];
__device__ __align__(16) float g_er2[NN];
__device__ __align__(16) float g_ew[NE * NH];      // per-edge softmax numerators
__device__ __align__(16) float g_a0[NN * INF_];    // tf32-rounded in_feat
__device__ __align__(16) float g_w0[INF_ * HID];   // tf32-rounded weights
__device__ __align__(16) float g_w1[HID * HID];
__device__ __align__(16) float g_w2[HID * NCLS];
__device__ int g_deg[NN];
__device__ int g_cursor[NN];
__device__ int g_rowptr[NN + 1];
__device__ int g_esrc[NE];
__device__ int g_edst[NE];

// ---------------- bit casts ----------------
__device__ __forceinline__ uint32_t h2_to_u32(half2 h) {
    uint32_t u;
    memcpy(&u, &h, 4);
    return u;
}
__device__ __forceinline__ half2 u32_to_h2(uint32_t u) {
    half2 h;
    memcpy(&h, &u, 4);
    return h;
}

// ---------------- CSR build ----------------
__global__ void k_zero(int* p, int n) {
    int i = blockIdx.x * blockDim.x + threadIdx.x;
    if (i < n) p[i] = 0;
}

__global__ void k_hist(const int* __restrict__ dst, int* deg, int E) {
    int i = blockIdx.x * blockDim.x + threadIdx.x;
    if (i < E) atomicAdd(&deg[dst[i]], 1);
}

__global__ void k_scan(const int* __restrict__ deg, int* __restrict__ rowptr, int n) {
    __shared__ int wsum[32];
    __shared__ int carry;
    int t = threadIdx.x, lane = t & 31, wid = t >> 5;
    if (t == 0) carry = 0;
    __syncthreads();
    for (int base = 0; base < n; base += blockDim.x) {
        int i = base + t;
        int v = (i < n) ? deg[i] : 0;
        int x = v;
#pragma unroll
        for (int o = 1; o < 32; o <<= 1) {
            int y = __shfl_up_sync(0xffffffffu, x, o);
            if (lane >= o) x += y;
        }
        if (lane == 31) wsum[wid] = x;
        __syncthreads();
        if (wid == 0) {
            int s = (lane < (int)(blockDim.x >> 5)) ? wsum[lane] : 0;
#pragma unroll
            for (int o = 1; o < 32; o <<= 1) {
                int y = __shfl_up_sync(0xffffffffu, s, o);
                if (lane >= o) s += y;
            }
            wsum[lane] = s;
        }
        __syncthreads();
        int woff = (wid == 0) ? 0 : wsum[wid - 1];
        int excl = carry + woff + x - v;
        if (i < n) rowptr[i] = excl;
        int total = wsum[(blockDim.x >> 5) - 1];
        __syncthreads();
        if (t == 0) carry += total;
        __syncthreads();
    }
    if (threadIdx.x == 0) rowptr[n] = carry;
}

__global__ void k_copy(int* __restrict__ d, const int* __restrict__ s, int n) {
    int i = blockIdx.x * blockDim.x + threadIdx.x;
    if (i < n) d[i] = s[i];
}

__global__ void k_scatter(const int* __restrict__ dst, const int* __restrict__ src,
                          int* cursor, int* __restrict__ esrc, int* __restrict__ edst,
                          int E) {
    int i = blockIdx.x * blockDim.x + threadIdx.x;
    if (i < E) {
        int d = dst[i];
        int p = atomicAdd(&cursor[d], 1);
        esrc[p] = src[i];
        edst[p] = d;
    }
}

// ---------------- tf32 pre-round (elementwise, vectorized) ----------------
__device__ __forceinline__ uint32_t f2tf(float f) {
    uint32_t u;
    asm("cvt.rna.tf32.f32 %0, %1;" : "=r"(u) : "f"(f));
    return u;
}
__device__ __forceinline__ float f2tff(float f) { return __uint_as_float(f2tf(f)); }

__global__ void k_cvt(float* __restrict__ dst, const float* __restrict__ src, int n4) {
    int i = blockIdx.x * blockDim.x + threadIdx.x;
    if (i >= n4) return;
    float4 v = ((const float4*)src)[i];
    v.x = f2tff(v.x); v.y = f2tff(v.y); v.z = f2tff(v.z); v.w = f2tff(v.w);
    ((float4*)dst)[i] = v;
}

// ---------------- TF32 tensor-core GEMM, cp.async 4-stage pipeline ----------------
#define BM 128
#define BN 128
#define BK 16
#define NSTAGE 4
#define A_STRIDE 20
#define B_STRIDE 136
#define A_STAGE_W (BM * A_STRIDE)
#define B_STAGE_W (BK * B_STRIDE)
#define SMEM_BYTES ((NSTAGE * (A_STAGE_W + B_STAGE_W)) * 4)

__device__ __forceinline__ void mma8(float* c, const uint32_t* a, const uint32_t* b) {
    asm volatile(
        "mma.sync.aligned.m16n8k8.row.col.f32.tf32.tf32.f32 "
        "{%0,%1,%2,%3}, {%4,%5,%6,%7}, {%8,%9}, {%0,%1,%2,%3};"
        : "+f"(c[0]), "+f"(c[1]), "+f"(c[2]), "+f"(c[3])
        : "r"(a[0]), "r"(a[1]), "r"(a[2]), "r"(a[3]), "r"(b[0]), "r"(b[1]));
}

__device__ __forceinline__ void cp16(uint32_t dst, const void* src, bool pred) {
    int sz = pred ? 16 : 0;
    asm volatile("cp.async.cg.shared.global [%0], [%1], 16, %2;"
                 :: "r"(dst), "l"(src), "r"(sz));
}
__device__ __forceinline__ void cp_commit() {
    asm volatile("cp.async.commit_group;");
}
template <int N>
__device__ __forceinline__ void cp_wait() {
    asm volatile("cp.async.wait_group %0;" :: "n"(N));
}

__global__ void __launch_bounds__(256) k_mma(const float* __restrict__ A,
                                             const float* __restrict__ B,
                                             float* __restrict__ C,
                                             int M, int N, int K) {
    extern __shared__ float smem[];
    uint32_t sbase;
    asm("{ .reg .u64 t; cvta.to.shared.u64 t, %1; cvt.u32.u64 %0, t; }"
        : "=r"(sbase) : "l"(smem));

    int tid = threadIdx.x;
    int warp = tid >> 5, lane = tid & 31;
    int gid = lane >> 2, tg = lane & 3;
    int wm = warp >> 2, wn = warp & 3;
    int m0 = blockIdx.x * BM, n0 = blockIdx.y * BN;

    int ar0 = tid >> 2, ar1 = ar0 + 64;
    int akc = (tid & 3) * 4;
    int bk0 = tid >> 5, bk1 = bk0 + 8;
    int bnc = (tid & 31) * 4;
    bool bok = (n0 + bnc + 4 <= N);

    float acc[4][4][4];
#pragma unroll
    for (int mi = 0; mi < 4; mi++)
#pragma unroll
        for (int ni = 0; ni < 4; ni++)
#pragma unroll
            for (int r = 0; r < 4; r++) acc[mi][ni][r] = 0.f;

    int kTiles = K / BK;

#define FILL_STAGE(s, kt)                                                             \
    do {                                                                              \
        int k0 = (kt) * BK;                                                           \
        uint32_t abase = sbase + (uint32_t)(s) * (A_STAGE_W * 4);                     \
        uint32_t bbase = sbase + (uint32_t)(NSTAGE * A_STAGE_W + (s) * B_STAGE_W) * 4;\
        cp16(abase + (ar0 * A_STRIDE + akc) * 4,                                      \
             A + (size_t)(m0 + ar0) * K + k0 + akc, m0 + ar0 < M);                    \
        cp16(abase + (ar1 * A_STRIDE + akc) * 4,                                      \
             A + (size_t)(m0 + ar1) * K + k0 + akc, m0 + ar1 < M);                    \
        cp16(bbase + (bk0 * B_STRIDE + bnc) * 4,                                      \
             B + (size_t)(k0 + bk0) * N + n0 + bnc, bok);                             \
        cp16(bbase + (bk1 * B_STRIDE + bnc) * 4,                                      \
             B + (size_t)(k0 + bk1) * N + n0 + bnc, bok);                             \
    } while (0)

#pragma unroll
    for (int s = 0; s < NSTAGE - 1; s++) {
        if (s < kTiles) FILL_STAGE(s, s);
        cp_commit();
    }

    const uint32_t* As = (const uint32_t*)smem;
    const uint32_t* Bs = (const uint32_t*)smem + NSTAGE * A_STAGE_W;

    for (int kt = 0; kt < kTiles; kt++) {
        cp_wait<NSTAGE - 2>();
        __syncthreads();

        int nkt = kt + NSTAGE - 1;
        if (nkt < kTiles) FILL_STAGE(nkt % NSTAGE, nkt);
        cp_commit();

        int buf = kt % NSTAGE;
        const uint32_t* Ab = As + buf * A_STAGE_W;
        const uint32_t* Bb = Bs + buf * B_STAGE_W;
#pragma unroll
        for (int ks = 0; ks < BK; ks += 8) {
            uint32_t af[4][4], bf[4][2];
#pragma unroll
            for (int mi = 0; mi < 4; mi++) {
                int mr = wm * 64 + mi * 16 + gid;
                af[mi][0] = Ab[mr * A_STRIDE + ks + tg];
                af[mi][1] = Ab[(mr + 8) * A_STRIDE + ks + tg];
                af[mi][2] = Ab[mr * A_STRIDE + ks + tg + 4];
                af[mi][3] = Ab[(mr + 8) * A_STRIDE + ks + tg + 4];
            }
#pragma unroll
            for (int ni = 0; ni < 4; ni++) {
                int nc = wn * 32 + ni * 8 + gid;
                bf[ni][0] = Bb[(ks + tg) * B_STRIDE + nc];
                bf[ni][1] = Bb[(ks + tg + 4) * B_STRIDE + nc];
            }
#pragma unroll
            for (int mi = 0; mi < 4; mi++)
#pragma unroll
                for (int ni = 0; ni < 4; ni++) mma8(acc[mi][ni], af[mi], bf[ni]);
        }
        __syncthreads();
    }

#pragma unroll
    for (int mi = 0; mi < 4; mi++) {
        int r0 = m0 + wm * 64 + mi * 16 + gid;
#pragma unroll
        for (int ni = 0; ni < 4; ni++) {
            int c0 = n0 + wn * 32 + ni * 8 + tg * 2;
            if (r0 < M) {
                if (c0 < N) C[(size_t)r0 * N + c0] = acc[mi][ni][0];
                if (c0 + 1 < N) C[(size_t)r0 * N + c0 + 1] = acc[mi][ni][1];
            }
            if (r0 + 8 < M) {
                if (c0 < N) C[(size_t)(r0 + 8) * N + c0] = acc[mi][ni][2];
                if (c0 + 1 < N) C[(size_t)(r0 + 8) * N + c0 + 1] = acc[mi][ni][3];
            }
        }
    }
}

// ---------------- helpers ----------------
__device__ __forceinline__ float warp_sum(float v) {
#pragma unroll
    for (int o = 16; o > 0; o >>= 1) v += __shfl_xor_sync(0xffffffffu, v, o);
    return v;
}
__device__ __forceinline__ float leaky(float x) { return x > 0.f ? x : NEG_SLOPE * x; }

// ---------------- prep: el/er projection + fp16 feat copy (one read) ----------------
// warp per node; lane owns cols [lane*8, lane*8+8), head = lane>>2.
__global__ void k_prep(const float* __restrict__ feat, const float* __restrict__ al,
                       const float* __restrict__ ar, float* __restrict__ el,
                       float* __restrict__ er, __half* __restrict__ feath, int n) {
    int node = (blockIdx.x * blockDim.x + threadIdx.x) >> 5;
    int lane = threadIdx.x & 31;
    if (node >= n) return;
    int col = lane * 8;
    int head = lane >> 2;
    const float* f = feat + (size_t)node * HID + col;
    float4 v0 = *(const float4*)f;
    float4 v1 = *(const float4*)(f + 4);

    // fp16 copy (packed, same layout)
    uint4 pk;
    pk.x = h2_to_u32(__floats2half2_rn(v0.x, v0.y));
    pk.y = h2_to_u32(__floats2half2_rn(v0.z, v0.w));
    pk.z = h2_to_u32(__floats2half2_rn(v1.x, v1.y));
    pk.w = h2_to_u32(__floats2half2_rn(v1.z, v1.w));
    *((uint4*)(feath + (size_t)node * HID + col)) = pk;

    // el/er partials over this lane's 8 cols (al/ar indexed by absolute col)
    float4 a0 = *(const float4*)(al + col);
    float4 a1 = *(const float4*)(al + col + 4);
    float4 r0 = *(const float4*)(ar + col);
    float4 r1 = *(const float4*)(ar + col + 4);
    float sl = v0.x * a0.x + v0.y * a0.y + v0.z * a0.z + v0.w * a0.w +
               v1.x * a1.x + v1.y * a1.y + v1.z * a1.z + v1.w * a1.w;
    float sr = v0.x * r0.x + v0.y * r0.y + v0.z * r0.z + v0.w * r0.w +
               v1.x * r1.x + v1.y * r1.y + v1.z * r1.z + v1.w * r1.w;
    // reduce within group of 4 lanes (same head)
    sl += __shfl_xor_sync(0xffffffffu, sl, 1);
    sl += __shfl_xor_sync(0xffffffffu, sl, 2);
    sr += __shfl_xor_sync(0xffffffffu, sr, 1);
    sr += __shfl_xor_sync(0xffffffffu, sr, 2);
    if ((lane & 3) == 0) {
        el[node * NH + head] = sl;
        er[node * NH + head] = sr;
    }
}

__global__ void k_elr1(const float* __restrict__ feat2, const float* __restrict__ al,
                       const float* __restrict__ ar, float* __restrict__ el,
                       float* __restrict__ er, int n) {
    int w = (blockIdx.x * blockDim.x + threadIdx.x) >> 5;
    int lane = threadIdx.x & 31;
    if (w >= n) return;
    const float* f = feat2 + (size_t)w * NCLS;
    float sl = f[lane] * __ldg(al + lane);
    float sr = f[lane] * __ldg(ar + lane);
    if (lane < 8) {
        sl += f[32 + lane] * __ldg(al + 32 + lane);
        sr += f[32 + lane] * __ldg(ar + 32 + lane);
    }
    sl = warp_sum(sl);
    sr = warp_sum(sr);
    if (lane == 0) { el[w] = sl; er[w] = sr; }
}

// ---------------- edge weights (lane-parallel exp) ----------------
__global__ void k_w8(const float* __restrict__ el, const float* __restrict__ er,
                     const int* __restrict__ esrc, const int* __restrict__ edst,
                     float* __restrict__ ew, int E) {
    int i = blockIdx.x * blockDim.x + threadIdx.x;
    if (i >= E) return;
    int s = esrc[i], d = edst[i];
    float4 l0 = *(const float4*)(el + s * NH);
    float4 l1 = *(const float4*)(el + s * NH + 4);
    float4 r0 = *(const float4*)(er + d * NH);
    float4 r1 = *(const float4*)(er + d * NH + 4);
    float4 w0, w1;
    w0.x = __expf(leaky(l0.x + r0.x));
    w0.y = __expf(leaky(l0.y + r0.y));
    w0.z = __expf(leaky(l0.z + r0.z));
    w0.w = __expf(leaky(l0.w + r0.w));
    w1.x = __expf(leaky(l1.x + r1.x));
    w1.y = __expf(leaky(l1.y + r1.y));
    w1.z = __expf(leaky(l1.z + r1.z));
    w1.w = __expf(leaky(l1.w + r1.w));
    *(float4*)(ew + (size_t)i * NH) = w0;
    *(float4*)(ew + (size_t)i * NH + 4) = w1;
}

__global__ void k_w1(const float* __restrict__ el, const float* __restrict__ er,
                     const int* __restrict__ esrc, const int* __restrict__ edst,
                     float* __restrict__ ew, int E) {
    int i = blockIdx.x * blockDim.x + threadIdx.x;
    if (i >= E) return;
    ew[i] = __expf(leaky(el[esrc[i]] + er[edst[i]]));
}

// ---------------- aggregation: warp per dst node, fp16 gather ----------------
// lane owns cols [lane*8, lane*8+8) (head lane>>2): ONE uint4 (8 halves) per edge.
__global__ void k_agg8(const __half* __restrict__ feath, const float* __restrict__ ew,
                       const int* __restrict__ rowptr, const int* __restrict__ esrc,
                       const float* __restrict__ bias, float* __restrict__ out,
                       int n, int do_relu) {
    int node = (blockIdx.x * blockDim.x + threadIdx.x) >> 5;
    int lane = threadIdx.x & 31;
    if (node >= n) return;
    int beg = rowptr[node], end = rowptr[node + 1];
    int head = lane >> 2;
    int col = lane * 8;

    float acc[8];
#pragma unroll
    for (int r = 0; r < 8; r++) acc[r] = 0.f;
    float den = 0.f;

#pragma unroll 4
    for (int i = beg; i < end; i++) {
        int s = esrc[i];  // warp-uniform
        float w = ew[(size_t)i * NH + head];
        den += w;
        uint4 pk = *((const uint4*)(feath + (size_t)s * HID + col));
        float2 f0 = __half22float2(u32_to_h2(pk.x));
        float2 f1 = __half22float2(u32_to_h2(pk.y));
        float2 f2 = __half22float2(u32_to_h2(pk.z));
        float2 f3 = __half22float2(u32_to_h2(pk.w));
        acc[0] = fmaf(w, f0.x, acc[0]); acc[1] = fmaf(w, f0.y, acc[1]);
        acc[2] = fmaf(w, f1.x, acc[2]); acc[3] = fmaf(w, f1.y, acc[3]);
        acc[4] = fmaf(w, f2.x, acc[4]); acc[5] = fmaf(w, f2.y, acc[5]);
        acc[6] = fmaf(w, f3.x, acc[6]); acc[7] = fmaf(w, f3.y, acc[7]);
    }
    float inv = 1.f / fmaxf(den, 1e-9f);
    float4 b0 = *(const float4*)(bias + col);
    float4 b1 = *(const float4*)(bias + col + 4);
    float ob[8] = {b0.x, b0.y, b0.z, b0.w, b1.x, b1.y, b1.z, b1.w};
    float o[8];
#pragma unroll
    for (int r = 0; r < 8; r++) {
        float v = fmaf(acc[r], inv, ob[r]);
        if (do_relu) v = fmaxf(v, 0.f);
        o[r] = f2tff(v);  // round for the consuming GEMM
    }
    float* op = out + (size_t)node * HID + col;
    *(float4*)op = make_float4(o[0], o[1], o[2], o[3]);
    *(float4*)(op + 4) = make_float4(o[4], o[5], o[6], o[7]);
}

// output layer: 1 head, 40 dims; lane<10 owns float4 cols [lane*4, lane*4+4)
__global__ void k_agg1(const float* __restrict__ feat2, const float* __restrict__ ew,
                       const int* __restrict__ rowptr, const int* __restrict__ esrc,
                       const float* __restrict__ bias, float* __restrict__ out, int n) {
    int node = (blockIdx.x * blockDim.x + threadIdx.x) >> 5;
    int lane = threadIdx.x & 31;
    if (node >= n) return;
    int beg = rowptr[node], end = rowptr[node + 1];

    float4 acc = make_float4(0.f, 0.f, 0.f, 0.f);
    float den = 0.f;
#pragma unroll 4
    for (int i = beg; i < end; i++) {
        int s = esrc[i];
        float w = ew[i];
        den += w;
        if (lane < 10) {
            float4 f = *(const float4*)(feat2 + (size_t)s * NCLS + lane * 4);
            acc.x = fmaf(w, f.x, acc.x); acc.y = fmaf(w, f.y, acc.y);
            acc.z = fmaf(w, f.z, acc.z); acc.w = fmaf(w, f.w, acc.w);
        }
    }
    float inv = 1.f / fmaxf(den, 1e-9f);
    if (lane < 10) {
        float4 b = *(const float4*)(bias + lane * 4);
        float4 o;
        o.x = fmaf(acc.x, inv, b.x); o.y = fmaf(acc.y, inv, b.y);
        o.z = fmaf(acc.z, inv, b.z); o.w = fmaf(acc.w, inv, b.w);
        *(float4*)(out + (size_t)node * NCLS + lane * 4) = o;
    }
}

// ---------------- host ----------------
extern "C" void kernel_launch(void* const* d_in, const int* in_sizes, int n_in,
                              void* d_out, int out_size) {
    const float* in_feat = (const float*)d_in[0];
    const int*   src     = (const int*)d_in[1];
    const int*   dst     = (const int*)d_in[2];
    const float* W0  = (const float*)d_in[3];
    const float* al0 = (const float*)d_in[4];
    const float* ar0 = (const float*)d_in[5];
    const float* b0  = (const float*)d_in[6];
    const float* W1  = (const float*)d_in[7];
    const float* al1 = (const float*)d_in[8];
    const float* ar1 = (const float*)d_in[9];
    const float* b1  = (const float*)d_in[10];
    const float* W2  = (const float*)d_in[11];
    const float* al2 = (const float*)d_in[12];
    const float* ar2 = (const float*)d_in[13];
    const float* b2  = (const float*)d_in[14];
    float* out = (float*)d_out;

    int n = NN;
    int E = in_sizes[1];

    float *feat, *h, *feat2, *el, *er, *el2, *er2, *ew, *a0, *w0, *w1, *w2;
    __half* feath;
    int *deg, *cur, *rp, *esrc, *edst;
    cudaGetSymbolAddress((void**)&feat, g_feat);
    cudaGetSymbolAddress((void**)&feath, g_feath);
    cudaGetSymbolAddress((void**)&h, g_h);
    cudaGetSymbolAddress((void**)&feat2, g_feat2);
    cudaGetSymbolAddress((void**)&el, g_el);
    cudaGetSymbolAddress((void**)&er, g_er);
    cudaGetSymbolAddress((void**)&el2, g_el2);
    cudaGetSymbolAddress((void**)&er2, g_er2);
    cudaGetSymbolAddress((void**)&ew, g_ew);
    cudaGetSymbolAddress((void**)&a0, g_a0);
    cudaGetSymbolAddress((void**)&w0, g_w0);
    cudaGetSymbolAddress((void**)&w1, g_w1);
    cudaGetSymbolAddress((void**)&w2, g_w2);
    cudaGetSymbolAddress((void**)&deg, g_deg);
    cudaGetSymbolAddress((void**)&cur, g_cursor);
    cudaGetSymbolAddress((void**)&rp, g_rowptr);
    cudaGetSymbolAddress((void**)&esrc, g_esrc);
    cudaGetSymbolAddress((void**)&edst, g_edst);

    static int attr_done = 0;
    if (!attr_done) {
        cudaFuncSetAttribute(k_mma, cudaFuncAttributeMaxDynamicSharedMemorySize,
                             SMEM_BYTES);
        attr_done = 1;
    }

    // CSR by dst
    k_zero<<<(n + 255) / 256, 256>>>(deg, n);
    k_hist<<<(E + 255) / 256, 256>>>(dst, deg, E);
    k_scan<<<1, 1024>>>(deg, rp, n);
    k_copy<<<(n + 255) / 256, 256>>>(cur, rp, n);
    k_scatter<<<(E + 255) / 256, 256>>>(dst, src, cur, esrc, edst, E);

    // pre-round GEMM inputs to tf32
    k_cvt<<<(NN * INF_ / 4 + 255) / 256, 256>>>(a0, in_feat, NN * INF_ / 4);
    k_cvt<<<(INF_ * HID / 4 + 255) / 256, 256>>>(w0, W0, INF_ * HID / 4);
    k_cvt<<<(HID * HID / 4 + 255) / 256, 256>>>(w1, W1, HID * HID / 4);
    k_cvt<<<(HID * NCLS / 4 + 255) / 256, 256>>>(w2, W2, HID * NCLS / 4);

    int nwarp_blocks = (n + 7) / 8;
    int eblocks = (E + 255) / 256;

    // layer 0
    {
        dim3 g((n + BM - 1) / BM, (HID + BN - 1) / BN);
        k_mma<<<g, 256, SMEM_BYTES>>>(a0, w0, feat, n, HID, INF_);
        k_prep<<<nwarp_blocks, 256>>>(feat, al0, ar0, el, er, feath, n);
        k_w8<<<eblocks, 256>>>(el, er, esrc, edst, ew, E);
        k_agg8<<<nwarp_blocks, 256>>>(feath, ew, rp, esrc, b0, h, n, 1);
    }
    // layer 1 (h already tf32-rounded by k_agg8)
    {
        dim3 g((n + BM - 1) / BM, (HID + BN - 1) / BN);
        k_mma<<<g, 256, SMEM_BYTES>>>(h, w1, feat, n, HID, HID);
        k_prep<<<nwarp_blocks, 256>>>(feat, al1, ar1, el, er, feath, n);
        k_w8<<<eblocks, 256>>>(el, er, esrc, edst, ew, E);
        k_agg8<<<nwarp_blocks, 256>>>(feath, ew, rp, esrc, b1, h, n, 1);
    }
    // output layer (1 head, 40 classes)
    {
        dim3 g((n + BM - 1) / BM, (NCLS + BN - 1) / BN);
        k_mma<<<g, 256, SMEM_BYTES>>>(h, w2, feat2, n, NCLS, HID);
        k_elr1<<<nwarp_blocks, 256>>>(feat2, al2, ar2, el2, er2, n);
        k_w1<<<eblocks, 256>>>(el2, er2, esrc, edst, ew, E);
        k_agg1<<<nwarp_blocks, 256>>>(feat2, ew, rp, esrc, b2, out, n);
    }
}

// round 10
// speedup vs baseline: 2.6055x; 1.3023x over previous
#include <cuda_runtime.h>
#include <cuda_fp16.h>
#include <float.h>
#include <stdint.h>

// Problem constants (fixed shapes)
#define NN 50000
#define NE 800000
#define INF_ 512
#define HID 256
#define NH 8
#define HD 32
#define NCLS 40
#define NEG_SLOPE 0.2f

// ---------------- scratch (device globals; no allocs allowed) ----------------
__device__ __align__(16) float g_feat[NN * HID];
__device__ __align__(16) __half g_feath[NN * HID];   // fp16 copy for edge gather
__device__ __align__(16) __half g_hh[NN * HID];      // fp16 hidden activations (GEMM A)
__device__ __align__(16) float g_feat2[NN * NCLS];
__device__ __align__(16) float g_el[NN * NH];
__device__ __align__(16) float g_er[NN * NH];
__device__ __align__(16) float g_el2[NN];
__device__ __align__(16) float g_er2[NN];
__device__ __align__(16) float g_ew[NE * NH];        // per-edge softmax numerators
__device__ __align__(16) __half g_a0h[NN * INF_];    // fp16 in_feat
__device__ __align__(16) __half g_w0h[INF_ * HID];   // fp16 weights
__device__ __align__(16) __half g_w1h[HID * HID];
__device__ __align__(16) __half g_w2h[HID * NCLS];
__device__ int g_deg[NN];
__device__ int g_cursor[NN];
__device__ int g_rowptr[NN + 1];
__device__ int g_esrc[NE];
__device__ int g_edst[NE];

// ---------------- bit casts ----------------
__device__ __forceinline__ uint32_t h2_to_u32(half2 h) {
    uint32_t u;
    memcpy(&u, &h, 4);
    return u;
}
__device__ __forceinline__ half2 u32_to_h2(uint32_t u) {
    half2 h;
    memcpy(&h, &u, 4);
    return h;
}

// ---------------- CSR build ----------------
__global__ void k_zero(int* p, int n) {
    int i = blockIdx.x * blockDim.x + threadIdx.x;
    if (i < n) p[i] = 0;
}

__global__ void k_hist(const int* __restrict__ dst, int* deg, int E) {
    int i = blockIdx.x * blockDim.x + threadIdx.x;
    if (i < E) atomicAdd(&deg[dst[i]], 1);
}

__global__ void k_scan(const int* __restrict__ deg, int* __restrict__ rowptr, int n) {
    __shared__ int wsum[32];
    __shared__ int carry;
    int t = threadIdx.x, lane = t & 31, wid = t >> 5;
    if (t == 0) carry = 0;
    __syncthreads();
    for (int base = 0; base < n; base += blockDim.x) {
        int i = base + t;
        int v = (i < n) ? deg[i] : 0;
        int x = v;
#pragma unroll
        for (int o = 1; o < 32; o <<= 1) {
            int y = __shfl_up_sync(0xffffffffu, x, o);
            if (lane >= o) x += y;
        }
        if (lane == 31) wsum[wid] = x;
        __syncthreads();
        if (wid == 0) {
            int s = (lane < (int)(blockDim.x >> 5)) ? wsum[lane] : 0;
#pragma unroll
            for (int o = 1; o < 32; o <<= 1) {
                int y = __shfl_up_sync(0xffffffffu, s, o);
                if (lane >= o) s += y;
            }
            wsum[lane] = s;
        }
        __syncthreads();
        int woff = (wid == 0) ? 0 : wsum[wid - 1];
        int excl = carry + woff + x - v;
        if (i < n) rowptr[i] = excl;
        int total = wsum[(blockDim.x >> 5) - 1];
        __syncthreads();
        if (t == 0) carry += total;
        __syncthreads();
    }
    if (threadIdx.x == 0) rowptr[n] = carry;
}

__global__ void k_copy(int* __restrict__ d, const int* __restrict__ s, int n) {
    int i = blockIdx.x * blockDim.x + threadIdx.x;
    if (i < n) d[i] = s[i];
}

__global__ void k_scatter(const int* __restrict__ dst, const int* __restrict__ src,
                          int* cursor, int* __restrict__ esrc, int* __restrict__ edst,
                          int E) {
    int i = blockIdx.x * blockDim.x + threadIdx.x;
    if (i < E) {
        int d = dst[i];
        int p = atomicAdd(&cursor[d], 1);
        esrc[p] = src[i];
        edst[p] = d;
    }
}

// ---------------- fp32 -> fp16 convert (8 elems/thread) ----------------
__global__ void k_cvth(__half* __restrict__ dst, const float* __restrict__ src, int n8) {
    int i = blockIdx.x * blockDim.x + threadIdx.x;
    if (i >= n8) return;
    float4 v0 = ((const float4*)src)[i * 2];
    float4 v1 = ((const float4*)src)[i * 2 + 1];
    uint4 pk;
    pk.x = h2_to_u32(__floats2half2_rn(v0.x, v0.y));
    pk.y = h2_to_u32(__floats2half2_rn(v0.z, v0.w));
    pk.z = h2_to_u32(__floats2half2_rn(v1.x, v1.y));
    pk.w = h2_to_u32(__floats2half2_rn(v1.z, v1.w));
    ((uint4*)dst)[i] = pk;
}

// ---------------- FP16 tensor-core GEMM: C[M,N] = A[M,K] @ B[K,N] ----------------
// A, B fp16; C fp32. 128x128 tile, BK=32 halves, 8 warps (2x4) of 64x32,
// mma.m16n8k16 + ldmatrix, cp.async 4-stage pipeline.
#define BM 128
#define BN 128
#define BK 32
#define NSTAGE 4
#define ASTR 40    // halves per A smem row (pad 32 -> 40; 80B stride, ldmatrix conflict-free)
#define BSTR 136   // halves per B smem row (pad 128 -> 136; 272B stride)
#define A_ST_H (BM * ASTR)   // 5120 halves / stage
#define B_ST_H (BK * BSTR)   // 4352 halves / stage
#define SMEM_BYTES (NSTAGE * (A_ST_H + B_ST_H) * 2)  // 75776 B

__device__ __forceinline__ void ldsm4(uint32_t* r, uint32_t addr) {
    asm volatile("ldmatrix.sync.aligned.m8n8.x4.shared.b16 {%0,%1,%2,%3}, [%4];"
                 : "=r"(r[0]), "=r"(r[1]), "=r"(r[2]), "=r"(r[3]) : "r"(addr));
}
__device__ __forceinline__ void ldsm4t(uint32_t* r, uint32_t addr) {
    asm volatile("ldmatrix.sync.aligned.m8n8.x4.trans.shared.b16 {%0,%1,%2,%3}, [%4];"
                 : "=r"(r[0]), "=r"(r[1]), "=r"(r[2]), "=r"(r[3]) : "r"(addr));
}
__device__ __forceinline__ void mma16(float* c, const uint32_t* a, const uint32_t* b) {
    asm volatile(
        "mma.sync.aligned.m16n8k16.row.col.f32.f16.f16.f32 "
        "{%0,%1,%2,%3}, {%4,%5,%6,%7}, {%8,%9}, {%0,%1,%2,%3};"
        : "+f"(c[0]), "+f"(c[1]), "+f"(c[2]), "+f"(c[3])
        : "r"(a[0]), "r"(a[1]), "r"(a[2]), "r"(a[3]), "r"(b[0]), "r"(b[1]));
}

__device__ __forceinline__ void cp16(uint32_t dst, const void* src, bool pred) {
    int sz = pred ? 16 : 0;
    asm volatile("cp.async.cg.shared.global [%0], [%1], 16, %2;"
                 :: "r"(dst), "l"(src), "r"(sz));
}
__device__ __forceinline__ void cp_commit() {
    asm volatile("cp.async.commit_group;");
}
template <int N>
__device__ __forceinline__ void cp_wait() {
    asm volatile("cp.async.wait_group %0;" :: "n"(N));
}

__global__ void __launch_bounds__(256) k_mma_h(const __half* __restrict__ A,
                                               const __half* __restrict__ B,
                                               float* __restrict__ C,
                                               int M, int N, int K) {
    extern __shared__ __half smemh[];
    uint32_t sbase;
    asm("{ .reg .u64 t; cvta.to.shared.u64 t, %1; cvt.u32.u64 %0, t; }"
        : "=r"(sbase) : "l"(smemh));

    int tid = threadIdx.x;
    int warp = tid >> 5, lane = tid & 31;
    int gid = lane >> 2, tg = lane & 3;
    int wm = warp >> 2, wn = warp & 3;  // warp tile rows wm*64, cols wn*32
    int m0 = blockIdx.x * BM, n0 = blockIdx.y * BN;

    // fill decomposition (16B = 8 halves per cp.async)
    int ar = tid >> 2;                 // A row 0..63 (+64)
    int ac = (tid & 3) * 8;            // A k-col in halves
    int bk = tid >> 4;                 // B k-row 0..15 (+16)
    int bn = (tid & 15) * 8;           // B n-col in halves
    bool bok = (n0 + bn + 8 <= N);

    float acc[4][4][4];
#pragma unroll
    for (int mi = 0; mi < 4; mi++)
#pragma unroll
        for (int ni = 0; ni < 4; ni++)
#pragma unroll
            for (int r = 0; r < 4; r++) acc[mi][ni][r] = 0.f;

    int kTiles = K / BK;

#define FILL_STAGE_H(s, kt)                                                            \
    do {                                                                               \
        int k0 = (kt) * BK;                                                            \
        uint32_t abase = sbase + (uint32_t)(s) * (A_ST_H * 2);                         \
        uint32_t bbase = sbase + (uint32_t)(NSTAGE * A_ST_H + (s) * B_ST_H) * 2;       \
        cp16(abase + (ar * ASTR + ac) * 2,                                             \
             A + (size_t)(m0 + ar) * K + k0 + ac, m0 + ar < M);                        \
        cp16(abase + ((ar + 64) * ASTR + ac) * 2,                                      \
             A + (size_t)(m0 + ar + 64) * K + k0 + ac, m0 + ar + 64 < M);              \
        cp16(bbase + (bk * BSTR + bn) * 2,                                             \
             B + (size_t)(k0 + bk) * N + n0 + bn, bok);                                \
        cp16(bbase + ((bk + 16) * BSTR + bn) * 2,                                      \
             B + (size_t)(k0 + bk + 16) * N + n0 + bn, bok);                           \
    } while (0)

#pragma unroll
    for (int s = 0; s < NSTAGE - 1; s++) {
        if (s < kTiles) FILL_STAGE_H(s, s);
        cp_commit();
    }

    int lrow = lane & 7, lg = lane >> 3;

    for (int kt = 0; kt < kTiles; kt++) {
        cp_wait<NSTAGE - 2>();
        __syncthreads();

        int nkt = kt + NSTAGE - 1;
        if (nkt < kTiles) FILL_STAGE_H(nkt % NSTAGE, nkt);
        cp_commit();

        int buf = kt % NSTAGE;
        uint32_t abase = sbase + (uint32_t)buf * (A_ST_H * 2);
        uint32_t bbase = sbase + (uint32_t)(NSTAGE * A_ST_H + buf * B_ST_H) * 2;

#pragma unroll
        for (int kstep = 0; kstep < 2; kstep++) {
            uint32_t af[4][4], bf[4][2];
            int colA = kstep * 16 + (lg >> 1) * 8;
#pragma unroll
            for (int mi = 0; mi < 4; mi++) {
                int row = wm * 64 + mi * 16 + (lg & 1) * 8 + lrow;
                ldsm4(af[mi], abase + (uint32_t)(row * ASTR + colA) * 2);
            }
            int rowB = kstep * 16 + (lg & 1) * 8 + lrow;
#pragma unroll
            for (int np = 0; np < 2; np++) {
                uint32_t t[4];
                int colB = wn * 32 + np * 16 + (lg >> 1) * 8;
                ldsm4t(t, bbase + (uint32_t)(rowB * BSTR + colB) * 2);
                bf[np * 2][0] = t[0]; bf[np * 2][1] = t[1];
                bf[np * 2 + 1][0] = t[2]; bf[np * 2 + 1][1] = t[3];
            }
#pragma unroll
            for (int mi = 0; mi < 4; mi++)
#pragma unroll
                for (int ni = 0; ni < 4; ni++) mma16(acc[mi][ni], af[mi], bf[ni]);
        }
        __syncthreads();
    }

    // epilogue (m16n8 C fragment: rows gid/gid+8, cols tg*2, tg*2+1)
#pragma unroll
    for (int mi = 0; mi < 4; mi++) {
        int r0 = m0 + wm * 64 + mi * 16 + gid;
#pragma unroll
        for (int ni = 0; ni < 4; ni++) {
            int c0 = n0 + wn * 32 + ni * 8 + tg * 2;
            if (r0 < M) {
                if (c0 < N) C[(size_t)r0 * N + c0] = acc[mi][ni][0];
                if (c0 + 1 < N) C[(size_t)r0 * N + c0 + 1] = acc[mi][ni][1];
            }
            if (r0 + 8 < M) {
                if (c0 < N) C[(size_t)(r0 + 8) * N + c0] = acc[mi][ni][2];
                if (c0 + 1 < N) C[(size_t)(r0 + 8) * N + c0 + 1] = acc[mi][ni][3];
            }
        }
    }
}

// ---------------- helpers ----------------
__device__ __forceinline__ float warp_sum(float v) {
#pragma unroll
    for (int o = 16; o > 0; o >>= 1) v += __shfl_xor_sync(0xffffffffu, v, o);
    return v;
}
__device__ __forceinline__ float leaky(float x) { return x > 0.f ? x : NEG_SLOPE * x; }

// ---------------- prep: el/er projection + fp16 feat copy (one read) ----------------
// warp per node; lane owns cols [lane*8, lane*8+8), head = lane>>2.
__global__ void k_prep(const float* __restrict__ feat, const float* __restrict__ al,
                       const float* __restrict__ ar, float* __restrict__ el,
                       float* __restrict__ er, __half* __restrict__ feath, int n) {
    int node = (blockIdx.x * blockDim.x + threadIdx.x) >> 5;
    int lane = threadIdx.x & 31;
    if (node >= n) return;
    int col = lane * 8;
    int head = lane >> 2;
    const float* f = feat + (size_t)node * HID + col;
    float4 v0 = *(const float4*)f;
    float4 v1 = *(const float4*)(f + 4);

    uint4 pk;
    pk.x = h2_to_u32(__floats2half2_rn(v0.x, v0.y));
    pk.y = h2_to_u32(__floats2half2_rn(v0.z, v0.w));
    pk.z = h2_to_u32(__floats2half2_rn(v1.x, v1.y));
    pk.w = h2_to_u32(__floats2half2_rn(v1.z, v1.w));
    *((uint4*)(feath + (size_t)node * HID + col)) = pk;

    float4 a0 = *(const float4*)(al + col);
    float4 a1 = *(const float4*)(al + col + 4);
    float4 r0 = *(const float4*)(ar + col);
    float4 r1 = *(const float4*)(ar + col + 4);
    float sl = v0.x * a0.x + v0.y * a0.y + v0.z * a0.z + v0.w * a0.w +
               v1.x * a1.x + v1.y * a1.y + v1.z * a1.z + v1.w * a1.w;
    float sr = v0.x * r0.x + v0.y * r0.y + v0.z * r0.z + v0.w * r0.w +
               v1.x * r1.x + v1.y * r1.y + v1.z * r1.z + v1.w * r1.w;
    sl += __shfl_xor_sync(0xffffffffu, sl, 1);
    sl += __shfl_xor_sync(0xffffffffu, sl, 2);
    sr += __shfl_xor_sync(0xffffffffu, sr, 1);
    sr += __shfl_xor_sync(0xffffffffu, sr, 2);
    if ((lane & 3) == 0) {
        el[node * NH + head] = sl;
        er[node * NH + head] = sr;
    }
}

__global__ void k_elr1(const float* __restrict__ feat2, const float* __restrict__ al,
                       const float* __restrict__ ar, float* __restrict__ el,
                       float* __restrict__ er, int n) {
    int w = (blockIdx.x * blockDim.x + threadIdx.x) >> 5;
    int lane = threadIdx.x & 31;
    if (w >= n) return;
    const float* f = feat2 + (size_t)w * NCLS;
    float sl = f[lane] * __ldg(al + lane);
    float sr = f[lane] * __ldg(ar + lane);
    if (lane < 8) {
        sl += f[32 + lane] * __ldg(al + 32 + lane);
        sr += f[32 + lane] * __ldg(ar + 32 + lane);
    }
    sl = warp_sum(sl);
    sr = warp_sum(sr);
    if (lane == 0) { el[w] = sl; er[w] = sr; }
}

// ---------------- edge weights (lane-parallel exp) ----------------
__global__ void k_w8(const float* __restrict__ el, const float* __restrict__ er,
                     const int* __restrict__ esrc, const int* __restrict__ edst,
                     float* __restrict__ ew, int E) {
    int i = blockIdx.x * blockDim.x + threadIdx.x;
    if (i >= E) return;
    int s = esrc[i], d = edst[i];
    float4 l0 = *(const float4*)(el + s * NH);
    float4 l1 = *(const float4*)(el + s * NH + 4);
    float4 r0 = *(const float4*)(er + d * NH);
    float4 r1 = *(const float4*)(er + d * NH + 4);
    float4 w0, w1;
    w0.x = __expf(leaky(l0.x + r0.x));
    w0.y = __expf(leaky(l0.y + r0.y));
    w0.z = __expf(leaky(l0.z + r0.z));
    w0.w = __expf(leaky(l0.w + r0.w));
    w1.x = __expf(leaky(l1.x + r1.x));
    w1.y = __expf(leaky(l1.y + r1.y));
    w1.z = __expf(leaky(l1.z + r1.z));
    w1.w = __expf(leaky(l1.w + r1.w));
    *(float4*)(ew + (size_t)i * NH) = w0;
    *(float4*)(ew + (size_t)i * NH + 4) = w1;
}

__global__ void k_w1(const float* __restrict__ el, const float* __restrict__ er,
                     const int* __restrict__ esrc, const int* __restrict__ edst,
                     float* __restrict__ ew, int E) {
    int i = blockIdx.x * blockDim.x + threadIdx.x;
    if (i >= E) return;
    ew[i] = __expf(leaky(el[esrc[i]] + er[edst[i]]));
}

// ---------------- aggregation: warp per dst node, fp16 gather, fp16 output ----------------
// lane owns cols [lane*8, lane*8+8) (head lane>>2): ONE uint4 (8 halves) per edge.
// Output written as fp16 (consumed directly by the next fp16 GEMM).
__global__ void k_agg8(const __half* __restrict__ feath, const float* __restrict__ ew,
                       const int* __restrict__ rowptr, const int* __restrict__ esrc,
                       const float* __restrict__ bias, __half* __restrict__ out,
                       int n, int do_relu) {
    int node = (blockIdx.x * blockDim.x + threadIdx.x) >> 5;
    int lane = threadIdx.x & 31;
    if (node >= n) return;
    int beg = rowptr[node], end = rowptr[node + 1];
    int head = lane >> 2;
    int col = lane * 8;

    float acc[8];
#pragma unroll
    for (int r = 0; r < 8; r++) acc[r] = 0.f;
    float den = 0.f;

#pragma unroll 4
    for (int i = beg; i < end; i++) {
        int s = esrc[i];  // warp-uniform
        float w = ew[(size_t)i * NH + head];
        den += w;
        uint4 pk = *((const uint4*)(feath + (size_t)s * HID + col));
        float2 f0 = __half22float2(u32_to_h2(pk.x));
        float2 f1 = __half22float2(u32_to_h2(pk.y));
        float2 f2 = __half22float2(u32_to_h2(pk.z));
        float2 f3 = __half22float2(u32_to_h2(pk.w));
        acc[0] = fmaf(w, f0.x, acc[0]); acc[1] = fmaf(w, f0.y, acc[1]);
        acc[2] = fmaf(w, f1.x, acc[2]); acc[3] = fmaf(w, f1.y, acc[3]);
        acc[4] = fmaf(w, f2.x, acc[4]); acc[5] = fmaf(w, f2.y, acc[5]);
        acc[6] = fmaf(w, f3.x, acc[6]); acc[7] = fmaf(w, f3.y, acc[7]);
    }
    float inv = 1.f / fmaxf(den, 1e-9f);
    float4 b0 = *(const float4*)(bias + col);
    float4 b1 = *(const float4*)(bias + col + 4);
    float ob[8] = {b0.x, b0.y, b0.z, b0.w, b1.x, b1.y, b1.z, b1.w};
    float o[8];
#pragma unroll
    for (int r = 0; r < 8; r++) {
        float v = fmaf(acc[r], inv, ob[r]);
        if (do_relu) v = fmaxf(v, 0.f);
        o[r] = v;
    }
    uint4 pk;
    pk.x = h2_to_u32(__floats2half2_rn(o[0], o[1]));
    pk.y = h2_to_u32(__floats2half2_rn(o[2], o[3]));
    pk.z = h2_to_u32(__floats2half2_rn(o[4], o[5]));
    pk.w = h2_to_u32(__floats2half2_rn(o[6], o[7]));
    *((uint4*)(out + (size_t)node * HID + col)) = pk;
}

// output layer: 1 head, 40 dims; lane<10 owns float4 cols [lane*4, lane*4+4)
__global__ void k_agg1(const float* __restrict__ feat2, const float* __restrict__ ew,
                       const int* __restrict__ rowptr, const int* __restrict__ esrc,
                       const float* __restrict__ bias, float* __restrict__ out, int n) {
    int node = (blockIdx.x * blockDim.x + threadIdx.x) >> 5;
    int lane = threadIdx.x & 31;
    if (node >= n) return;
    int beg = rowptr[node], end = rowptr[node + 1];

    float4 acc = make_float4(0.f, 0.f, 0.f, 0.f);
    float den = 0.f;
#pragma unroll 4
    for (int i = beg; i < end; i++) {
        int s = esrc[i];
        float w = ew[i];
        den += w;
        if (lane < 10) {
            float4 f = *(const float4*)(feat2 + (size_t)s * NCLS + lane * 4);
            acc.x = fmaf(w, f.x, acc.x); acc.y = fmaf(w, f.y, acc.y);
            acc.z = fmaf(w, f.z, acc.z); acc.w = fmaf(w, f.w, acc.w);
        }
    }
    float inv = 1.f / fmaxf(den, 1e-9f);
    if (lane < 10) {
        float4 b = *(const float4*)(bias + lane * 4);
        float4 o;
        o.x = fmaf(acc.x, inv, b.x); o.y = fmaf(acc.y, inv, b.y);
        o.z = fmaf(acc.z, inv, b.z); o.w = fmaf(acc.w, inv, b.w);
        *(float4*)(out + (size_t)node * NCLS + lane * 4) = o;
    }
}

// ---------------- host ----------------
extern "C" void kernel_launch(void* const* d_in, const int* in_sizes, int n_in,
                              void* d_out, int out_size) {
    const float* in_feat = (const float*)d_in[0];
    const int*   src     = (const int*)d_in[1];
    const int*   dst     = (const int*)d_in[2];
    const float* W0  = (const float*)d_in[3];
    const float* al0 = (const float*)d_in[4];
    const float* ar0 = (const float*)d_in[5];
    const float* b0  = (const float*)d_in[6];
    const float* W1  = (const float*)d_in[7];
    const float* al1 = (const float*)d_in[8];
    const float* ar1 = (const float*)d_in[9];
    const float* b1  = (const float*)d_in[10];
    const float* W2  = (const float*)d_in[11];
    const float* al2 = (const float*)d_in[12];
    const float* ar2 = (const float*)d_in[13];
    const float* b2  = (const float*)d_in[14];
    float* out = (float*)d_out;

    int n = NN;
    int E = in_sizes[1];

    float *feat, *feat2, *el, *er, *el2, *er2, *ew;
    __half *feath, *hh, *a0h, *w0h, *w1h, *w2h;
    int *deg, *cur, *rp, *esrc, *edst;
    cudaGetSymbolAddress((void**)&feat, g_feat);
    cudaGetSymbolAddress((void**)&feath, g_feath);
    cudaGetSymbolAddress((void**)&hh, g_hh);
    cudaGetSymbolAddress((void**)&feat2, g_feat2);
    cudaGetSymbolAddress((void**)&el, g_el);
    cudaGetSymbolAddress((void**)&er, g_er);
    cudaGetSymbolAddress((void**)&el2, g_el2);
    cudaGetSymbolAddress((void**)&er2, g_er2);
    cudaGetSymbolAddress((void**)&ew, g_ew);
    cudaGetSymbolAddress((void**)&a0h, g_a0h);
    cudaGetSymbolAddress((void**)&w0h, g_w0h);
    cudaGetSymbolAddress((void**)&w1h, g_w1h);
    cudaGetSymbolAddress((void**)&w2h, g_w2h);
    cudaGetSymbolAddress((void**)&deg, g_deg);
    cudaGetSymbolAddress((void**)&cur, g_cursor);
    cudaGetSymbolAddress((void**)&rp, g_rowptr);
    cudaGetSymbolAddress((void**)&esrc, g_esrc);
    cudaGetSymbolAddress((void**)&edst, g_edst);

    static int attr_done = 0;
    if (!attr_done) {
        cudaFuncSetAttribute(k_mma_h, cudaFuncAttributeMaxDynamicSharedMemorySize,
                             SMEM_BYTES);
        attr_done = 1;
    }

    // CSR by dst
    k_zero<<<(n + 255) / 256, 256>>>(deg, n);
    k_hist<<<(E + 255) / 256, 256>>>(dst, deg, E);
    k_scan<<<1, 1024>>>(deg, rp, n);
    k_copy<<<(n + 255) / 256, 256>>>(cur, rp, n);
    k_scatter<<<(E + 255) / 256, 256>>>(dst, src, cur, esrc, edst, E);

    // convert GEMM inputs to fp16
    k_cvth<<<(NN * INF_ / 8 + 255) / 256, 256>>>(a0h, in_feat, NN * INF_ / 8);
    k_cvth<<<(INF_ * HID / 8 + 255) / 256, 256>>>(w0h, W0, INF_ * HID / 8);
    k_cvth<<<(HID * HID / 8 + 255) / 256, 256>>>(w1h, W1, HID * HID / 8);
    k_cvth<<<(HID * NCLS / 8 + 255) / 256, 256>>>(w2h, W2, HID * NCLS / 8);

    int nwarp_blocks = (n + 7) / 8;
    int eblocks = (E + 255) / 256;

    // layer 0
    {
        dim3 g((n + BM - 1) / BM, (HID + BN - 1) / BN);
        k_mma_h<<<g, 256, SMEM_BYTES>>>(a0h, w0h, feat, n, HID, INF_);
        k_prep<<<nwarp_blocks, 256>>>(feat, al0, ar0, el, er, feath, n);
        k_w8<<<eblocks, 256>>>(el, er, esrc, edst, ew, E);
        k_agg8<<<nwarp_blocks, 256>>>(feath, ew, rp, esrc, b0, hh, n, 1);
    }
    // layer 1 (hh is fp16 from k_agg8)
    {
        dim3 g((n + BM - 1) / BM, (HID + BN - 1) / BN);
        k_mma_h<<<g, 256, SMEM_BYTES>>>(hh, w1h, feat, n, HID, HID);
        k_prep<<<nwarp_blocks, 256>>>(feat, al1, ar1, el, er, feath, n);
        k_w8<<<eblocks, 256>>>(el, er, esrc, edst, ew, E);
        k_agg8<<<nwarp_blocks, 256>>>(feath, ew, rp, esrc, b1, hh, n, 1);
    }
    // output layer (1 head, 40 classes)
    {
        dim3 g((n + BM - 1) / BM, (NCLS + BN - 1) / BN);
        k_mma_h<<<g, 256, SMEM_BYTES>>>(hh, w2h, feat2, n, NCLS, HID);
        k_elr1<<<nwarp_blocks, 256>>>(feat2, al2, ar2, el2, er2, n);
        k_w1<<<eblocks, 256>>>(el2, er2, esrc, edst, ew, E);
        k_agg1<<<nwarp_blocks, 256>>>(feat2, ew, rp, esrc, b2, out, n);
    }
}

// round 11
// speedup vs baseline: 2.9660x; 1.1384x over previous
#include <cuda_runtime.h>
#include <cuda_fp16.h>
#include <float.h>
#include <stdint.h>

// Problem constants (fixed shapes)
#define NN 50000
#define NE 800000
#define INF_ 512
#define HID 256
#define NH 8
#define HD 32
#define NCLS 40
#define NEG_SLOPE 0.2f

// ---------------- scratch (device globals; no allocs allowed) ----------------
__device__ __align__(16) __half g_feath[NN * HID];   // fp16 activations (GEMM out / gather in)
__device__ __align__(16) __half g_hh[NN * HID];      // fp16 hidden activations (GEMM A)
__device__ __align__(16) float g_feat2[NN * NCLS];
__device__ __align__(16) float g_el[NN * NH];
__device__ __align__(16) float g_er[NN * NH];
__device__ __align__(16) float g_el2[NN];
__device__ __align__(16) float g_er2[NN];
__device__ __align__(16) __half g_a0h[NN * INF_];    // fp16 in_feat
__device__ __align__(16) __half g_w0h[INF_ * HID];   // fp16 weights
__device__ __align__(16) __half g_w1h[HID * HID];
__device__ __align__(16) __half g_w2h[HID * NCLS];
__device__ int g_deg[NN];
__device__ int g_cursor[NN];
__device__ int g_rowptr[NN + 1];
__device__ int g_esrc[NE];

// ---------------- bit casts ----------------
__device__ __forceinline__ uint32_t h2_to_u32(half2 h) {
    uint32_t u;
    memcpy(&u, &h, 4);
    return u;
}
__device__ __forceinline__ half2 u32_to_h2(uint32_t u) {
    half2 h;
    memcpy(&h, &u, 4);
    return h;
}

// ---------------- CSR build ----------------
__global__ void k_zero(int* p, int n) {
    int i = blockIdx.x * blockDim.x + threadIdx.x;
    if (i < n) p[i] = 0;
}

__global__ void k_hist(const int* __restrict__ dst, int* deg, int E) {
    int i = blockIdx.x * blockDim.x + threadIdx.x;
    if (i < E) atomicAdd(&deg[dst[i]], 1);
}

__global__ void k_scan(const int* __restrict__ deg, int* __restrict__ rowptr,
                       int* __restrict__ cursor, int n) {
    __shared__ int wsum[32];
    __shared__ int carry;
    int t = threadIdx.x, lane = t & 31, wid = t >> 5;
    if (t == 0) carry = 0;
    __syncthreads();
    for (int base = 0; base < n; base += blockDim.x) {
        int i = base + t;
        int v = (i < n) ? deg[i] : 0;
        int x = v;
#pragma unroll
        for (int o = 1; o < 32; o <<= 1) {
            int y = __shfl_up_sync(0xffffffffu, x, o);
            if (lane >= o) x += y;
        }
        if (lane == 31) wsum[wid] = x;
        __syncthreads();
        if (wid == 0) {
            int s = (lane < (int)(blockDim.x >> 5)) ? wsum[lane] : 0;
#pragma unroll
            for (int o = 1; o < 32; o <<= 1) {
                int y = __shfl_up_sync(0xffffffffu, s, o);
                if (lane >= o) s += y;
            }
            wsum[lane] = s;
        }
        __syncthreads();
        int woff = (wid == 0) ? 0 : wsum[wid - 1];
        int excl = carry + woff + x - v;
        if (i < n) { rowptr[i] = excl; cursor[i] = excl; }
        int total = wsum[(blockDim.x >> 5) - 1];
        __syncthreads();
        if (t == 0) carry += total;
        __syncthreads();
    }
    if (threadIdx.x == 0) rowptr[n] = carry;
}

__global__ void k_scatter(const int* __restrict__ dst, const int* __restrict__ src,
                          int* cursor, int* __restrict__ esrc, int E) {
    int i = blockIdx.x * blockDim.x + threadIdx.x;
    if (i < E) {
        int p = atomicAdd(&cursor[dst[i]], 1);
        esrc[p] = src[i];
    }
}

// ---------------- fp32 -> fp16 convert (8 elems/thread) ----------------
__global__ void k_cvth(__half* __restrict__ dst, const float* __restrict__ src, int n8) {
    int i = blockIdx.x * blockDim.x + threadIdx.x;
    if (i >= n8) return;
    float4 v0 = ((const float4*)src)[i * 2];
    float4 v1 = ((const float4*)src)[i * 2 + 1];
    uint4 pk;
    pk.x = h2_to_u32(__floats2half2_rn(v0.x, v0.y));
    pk.y = h2_to_u32(__floats2half2_rn(v0.z, v0.w));
    pk.z = h2_to_u32(__floats2half2_rn(v1.x, v1.y));
    pk.w = h2_to_u32(__floats2half2_rn(v1.z, v1.w));
    ((uint4*)dst)[i] = pk;
}

// ---------------- FP16 tensor-core GEMM core ----------------
#define BM 128
#define BN 128
#define BK 32
#define NSTAGE 4
#define ASTR 40
#define BSTR 136
#define A_ST_H (BM * ASTR)
#define B_ST_H (BK * BSTR)
#define SMEM_BYTES (NSTAGE * (A_ST_H + B_ST_H) * 2)

__device__ __forceinline__ void ldsm4(uint32_t* r, uint32_t addr) {
    asm volatile("ldmatrix.sync.aligned.m8n8.x4.shared.b16 {%0,%1,%2,%3}, [%4];"
                 : "=r"(r[0]), "=r"(r[1]), "=r"(r[2]), "=r"(r[3]) : "r"(addr));
}
__device__ __forceinline__ void ldsm4t(uint32_t* r, uint32_t addr) {
    asm volatile("ldmatrix.sync.aligned.m8n8.x4.trans.shared.b16 {%0,%1,%2,%3}, [%4];"
                 : "=r"(r[0]), "=r"(r[1]), "=r"(r[2]), "=r"(r[3]) : "r"(addr));
}
__device__ __forceinline__ void mma16(float* c, const uint32_t* a, const uint32_t* b) {
    asm volatile(
        "mma.sync.aligned.m16n8k16.row.col.f32.f16.f16.f32 "
        "{%0,%1,%2,%3}, {%4,%5,%6,%7}, {%8,%9}, {%0,%1,%2,%3};"
        : "+f"(c[0]), "+f"(c[1]), "+f"(c[2]), "+f"(c[3])
        : "r"(a[0]), "r"(a[1]), "r"(a[2]), "r"(a[3]), "r"(b[0]), "r"(b[1]));
}
__device__ __forceinline__ void cp16(uint32_t dst, const void* src, bool pred) {
    int sz = pred ? 16 : 0;
    asm volatile("cp.async.cg.shared.global [%0], [%1], 16, %2;"
                 :: "r"(dst), "l"(src), "r"(sz));
}
__device__ __forceinline__ void cp_commit() {
    asm volatile("cp.async.commit_group;");
}
template <int N>
__device__ __forceinline__ void cp_wait() {
    asm volatile("cp.async.wait_group %0;" :: "n"(N));
}

// Shared mainloop; OUT_HALF selects fp16 vs fp32 epilogue.
template <int OUT_HALF>
__device__ __forceinline__ void mma_body(const __half* __restrict__ A,
                                         const __half* __restrict__ B,
                                         void* __restrict__ Cv,
                                         int M, int N, int K) {
    extern __shared__ __half smemh[];
    uint32_t sbase;
    asm("{ .reg .u64 t; cvta.to.shared.u64 t, %1; cvt.u32.u64 %0, t; }"
        : "=r"(sbase) : "l"(smemh));

    int tid = threadIdx.x;
    int warp = tid >> 5, lane = tid & 31;
    int gid = lane >> 2, tg = lane & 3;
    int wm = warp >> 2, wn = warp & 3;
    int m0 = blockIdx.x * BM, n0 = blockIdx.y * BN;

    int ar = tid >> 2;
    int ac = (tid & 3) * 8;
    int bk = tid >> 4;
    int bn = (tid & 15) * 8;
    bool bok = (n0 + bn + 8 <= N);

    float acc[4][4][4];
#pragma unroll
    for (int mi = 0; mi < 4; mi++)
#pragma unroll
        for (int ni = 0; ni < 4; ni++)
#pragma unroll
            for (int r = 0; r < 4; r++) acc[mi][ni][r] = 0.f;

    int kTiles = K / BK;

#define FILL_STAGE_H(s, kt)                                                            \
    do {                                                                               \
        int k0 = (kt) * BK;                                                            \
        uint32_t abase = sbase + (uint32_t)(s) * (A_ST_H * 2);                         \
        uint32_t bbase = sbase + (uint32_t)(NSTAGE * A_ST_H + (s) * B_ST_H) * 2;       \
        cp16(abase + (ar * ASTR + ac) * 2,                                             \
             A + (size_t)(m0 + ar) * K + k0 + ac, m0 + ar < M);                        \
        cp16(abase + ((ar + 64) * ASTR + ac) * 2,                                      \
             A + (size_t)(m0 + ar + 64) * K + k0 + ac, m0 + ar + 64 < M);              \
        cp16(bbase + (bk * BSTR + bn) * 2,                                             \
             B + (size_t)(k0 + bk) * N + n0 + bn, bok);                                \
        cp16(bbase + ((bk + 16) * BSTR + bn) * 2,                                      \
             B + (size_t)(k0 + bk + 16) * N + n0 + bn, bok);                           \
    } while (0)

#pragma unroll
    for (int s = 0; s < NSTAGE - 1; s++) {
        if (s < kTiles) FILL_STAGE_H(s, s);
        cp_commit();
    }

    int lrow = lane & 7, lg = lane >> 3;

    for (int kt = 0; kt < kTiles; kt++) {
        cp_wait<NSTAGE - 2>();
        __syncthreads();

        int nkt = kt + NSTAGE - 1;
        if (nkt < kTiles) FILL_STAGE_H(nkt % NSTAGE, nkt);
        cp_commit();

        int buf = kt % NSTAGE;
        uint32_t abase = sbase + (uint32_t)buf * (A_ST_H * 2);
        uint32_t bbase = sbase + (uint32_t)(NSTAGE * A_ST_H + buf * B_ST_H) * 2;

#pragma unroll
        for (int kstep = 0; kstep < 2; kstep++) {
            uint32_t af[4][4], bf[4][2];
            int colA = kstep * 16 + (lg >> 1) * 8;
#pragma unroll
            for (int mi = 0; mi < 4; mi++) {
                int row = wm * 64 + mi * 16 + (lg & 1) * 8 + lrow;
                ldsm4(af[mi], abase + (uint32_t)(row * ASTR + colA) * 2);
            }
            int rowB = kstep * 16 + (lg & 1) * 8 + lrow;
#pragma unroll
            for (int np = 0; np < 2; np++) {
                uint32_t t[4];
                int colB = wn * 32 + np * 16 + (lg >> 1) * 8;
                ldsm4t(t, bbase + (uint32_t)(rowB * BSTR + colB) * 2);
                bf[np * 2][0] = t[0]; bf[np * 2][1] = t[1];
                bf[np * 2 + 1][0] = t[2]; bf[np * 2 + 1][1] = t[3];
            }
#pragma unroll
            for (int mi = 0; mi < 4; mi++)
#pragma unroll
                for (int ni = 0; ni < 4; ni++) mma16(acc[mi][ni], af[mi], bf[ni]);
        }
        __syncthreads();
    }

#pragma unroll
    for (int mi = 0; mi < 4; mi++) {
        int r0 = m0 + wm * 64 + mi * 16 + gid;
#pragma unroll
        for (int ni = 0; ni < 4; ni++) {
            int c0 = n0 + wn * 32 + ni * 8 + tg * 2;
            if (OUT_HALF) {
                __half* C = (__half*)Cv;
                if (r0 < M && c0 + 1 < N + 1 && c0 < N) {
                    half2 h = __floats2half2_rn(acc[mi][ni][0], acc[mi][ni][1]);
                    *(half2*)(C + (size_t)r0 * N + c0) = h;
                }
                if (r0 + 8 < M && c0 < N) {
                    half2 h = __floats2half2_rn(acc[mi][ni][2], acc[mi][ni][3]);
                    *(half2*)(C + (size_t)(r0 + 8) * N + c0) = h;
                }
            } else {
                float* C = (float*)Cv;
                if (r0 < M) {
                    if (c0 < N) C[(size_t)r0 * N + c0] = acc[mi][ni][0];
                    if (c0 + 1 < N) C[(size_t)r0 * N + c0 + 1] = acc[mi][ni][1];
                }
                if (r0 + 8 < M) {
                    if (c0 < N) C[(size_t)(r0 + 8) * N + c0] = acc[mi][ni][2];
                    if (c0 + 1 < N) C[(size_t)(r0 + 8) * N + c0 + 1] = acc[mi][ni][3];
                }
            }
        }
    }
}

__global__ void __launch_bounds__(256) k_mma_hh(const __half* __restrict__ A,
                                                const __half* __restrict__ B,
                                                __half* __restrict__ C,
                                                int M, int N, int K) {
    mma_body<1>(A, B, C, M, N, K);
}
__global__ void __launch_bounds__(256) k_mma_hf(const __half* __restrict__ A,
                                                const __half* __restrict__ B,
                                                float* __restrict__ C,
                                                int M, int N, int K) {
    mma_body<0>(A, B, C, M, N, K);
}

// ---------------- helpers ----------------
__device__ __forceinline__ float warp_sum(float v) {
#pragma unroll
    for (int o = 16; o > 0; o >>= 1) v += __shfl_xor_sync(0xffffffffu, v, o);
    return v;
}
__device__ __forceinline__ float leaky(float x) { return x > 0.f ? x : NEG_SLOPE * x; }

// ---------------- prep: el/er projections from fp16 activations ----------------
// warp per node; lane owns cols [lane*8, lane*8+8), head = lane>>2.
__global__ void k_prep_h(const __half* __restrict__ feath, const float* __restrict__ al,
                         const float* __restrict__ ar, float* __restrict__ el,
                         float* __restrict__ er, int n) {
    int node = (blockIdx.x * blockDim.x + threadIdx.x) >> 5;
    int lane = threadIdx.x & 31;
    if (node >= n) return;
    int col = lane * 8;
    int head = lane >> 2;
    uint4 pk = *((const uint4*)(feath + (size_t)node * HID + col));
    float2 f0 = __half22float2(u32_to_h2(pk.x));
    float2 f1 = __half22float2(u32_to_h2(pk.y));
    float2 f2 = __half22float2(u32_to_h2(pk.z));
    float2 f3 = __half22float2(u32_to_h2(pk.w));

    float4 a0 = *(const float4*)(al + col);
    float4 a1 = *(const float4*)(al + col + 4);
    float4 r0 = *(const float4*)(ar + col);
    float4 r1 = *(const float4*)(ar + col + 4);
    float sl = f0.x * a0.x + f0.y * a0.y + f1.x * a0.z + f1.y * a0.w +
               f2.x * a1.x + f2.y * a1.y + f3.x * a1.z + f3.y * a1.w;
    float sr = f0.x * r0.x + f0.y * r0.y + f1.x * r0.z + f1.y * r0.w +
               f2.x * r1.x + f2.y * r1.y + f3.x * r1.z + f3.y * r1.w;
    sl += __shfl_xor_sync(0xffffffffu, sl, 1);
    sl += __shfl_xor_sync(0xffffffffu, sl, 2);
    sr += __shfl_xor_sync(0xffffffffu, sr, 1);
    sr += __shfl_xor_sync(0xffffffffu, sr, 2);
    if ((lane & 3) == 0) {
        el[node * NH + head] = sl;
        er[node * NH + head] = sr;
    }
}

__global__ void k_elr1(const float* __restrict__ feat2, const float* __restrict__ al,
                       const float* __restrict__ ar, float* __restrict__ el,
                       float* __restrict__ er, int n) {
    int w = (blockIdx.x * blockDim.x + threadIdx.x) >> 5;
    int lane = threadIdx.x & 31;
    if (w >= n) return;
    const float* f = feat2 + (size_t)w * NCLS;
    float sl = f[lane] * __ldg(al + lane);
    float sr = f[lane] * __ldg(ar + lane);
    if (lane < 8) {
        sl += f[32 + lane] * __ldg(al + 32 + lane);
        sr += f[32 + lane] * __ldg(ar + 32 + lane);
    }
    sl = warp_sum(sl);
    sr = warp_sum(sr);
    if (lane == 0) { el[w] = sl; er[w] = sr; }
}

// ---------------- aggregation: warp per dst node, inline softmax weights ----------------
// lane owns cols [lane*8, lane*8+8) (head lane>>2). Edge weight computed inline:
// w = exp(leaky(el[src][head] + er[node][head])); den accumulated per lane.
__global__ void k_agg8(const __half* __restrict__ feath, const float* __restrict__ el,
                       const float* __restrict__ er, const int* __restrict__ rowptr,
                       const int* __restrict__ esrc, const float* __restrict__ bias,
                       __half* __restrict__ out, int n, int do_relu) {
    int node = (blockIdx.x * blockDim.x + threadIdx.x) >> 5;
    int lane = threadIdx.x & 31;
    if (node >= n) return;
    int beg = rowptr[node], end = rowptr[node + 1];
    int head = lane >> 2;
    int col = lane * 8;
    float ern = __ldg(er + node * NH + head);

    float acc[8];
#pragma unroll
    for (int r = 0; r < 8; r++) acc[r] = 0.f;
    float den = 0.f;

#pragma unroll 4
    for (int i = beg; i < end; i++) {
        int s = esrc[i];  // warp-uniform
        float w = __expf(leaky(__ldg(el + s * NH + head) + ern));
        den += w;
        uint4 pk = *((const uint4*)(feath + (size_t)s * HID + col));
        float2 f0 = __half22float2(u32_to_h2(pk.x));
        float2 f1 = __half22float2(u32_to_h2(pk.y));
        float2 f2 = __half22float2(u32_to_h2(pk.z));
        float2 f3 = __half22float2(u32_to_h2(pk.w));
        acc[0] = fmaf(w, f0.x, acc[0]); acc[1] = fmaf(w, f0.y, acc[1]);
        acc[2] = fmaf(w, f1.x, acc[2]); acc[3] = fmaf(w, f1.y, acc[3]);
        acc[4] = fmaf(w, f2.x, acc[4]); acc[5] = fmaf(w, f2.y, acc[5]);
        acc[6] = fmaf(w, f3.x, acc[6]); acc[7] = fmaf(w, f3.y, acc[7]);
    }
    float inv = 1.f / fmaxf(den, 1e-9f);
    float4 b0 = *(const float4*)(bias + col);
    float4 b1 = *(const float4*)(bias + col + 4);
    float ob[8] = {b0.x, b0.y, b0.z, b0.w, b1.x, b1.y, b1.z, b1.w};
    float o[8];
#pragma unroll
    for (int r = 0; r < 8; r++) {
        float v = fmaf(acc[r], inv, ob[r]);
        if (do_relu) v = fmaxf(v, 0.f);
        o[r] = v;
    }
    uint4 pk;
    pk.x = h2_to_u32(__floats2half2_rn(o[0], o[1]));
    pk.y = h2_to_u32(__floats2half2_rn(o[2], o[3]));
    pk.z = h2_to_u32(__floats2half2_rn(o[4], o[5]));
    pk.w = h2_to_u32(__floats2half2_rn(o[6], o[7]));
    *((uint4*)(out + (size_t)node * HID + col)) = pk;
}

// output layer: 1 head, 40 dims; lane<10 owns float4 cols [lane*4, lane*4+4)
__global__ void k_agg1(const float* __restrict__ feat2, const float* __restrict__ el,
                       const float* __restrict__ er, const int* __restrict__ rowptr,
                       const int* __restrict__ esrc, const float* __restrict__ bias,
                       float* __restrict__ out, int n) {
    int node = (blockIdx.x * blockDim.x + threadIdx.x) >> 5;
    int lane = threadIdx.x & 31;
    if (node >= n) return;
    int beg = rowptr[node], end = rowptr[node + 1];
    float ern = er[node];

    float4 acc = make_float4(0.f, 0.f, 0.f, 0.f);
    float den = 0.f;
#pragma unroll 4
    for (int i = beg; i < end; i++) {
        int s = esrc[i];
        float w = __expf(leaky(__ldg(el + s) + ern));
        den += w;
        if (lane < 10) {
            float4 f = *(const float4*)(feat2 + (size_t)s * NCLS + lane * 4);
            acc.x = fmaf(w, f.x, acc.x); acc.y = fmaf(w, f.y, acc.y);
            acc.z = fmaf(w, f.z, acc.z); acc.w = fmaf(w, f.w, acc.w);
        }
    }
    float inv = 1.f / fmaxf(den, 1e-9f);
    if (lane < 10) {
        float4 b = *(const float4*)(bias + lane * 4);
        float4 o;
        o.x = fmaf(acc.x, inv, b.x); o.y = fmaf(acc.y, inv, b.y);
        o.z = fmaf(acc.z, inv, b.z); o.w = fmaf(acc.w, inv, b.w);
        *(float4*)(out + (size_t)node * NCLS + lane * 4) = o;
    }
}

// ---------------- host ----------------
extern "C" void kernel_launch(void* const* d_in, const int* in_sizes, int n_in,
                              void* d_out, int out_size) {
    const float* in_feat = (const float*)d_in[0];
    const int*   src     = (const int*)d_in[1];
    const int*   dst     = (const int*)d_in[2];
    const float* W0  = (const float*)d_in[3];
    const float* al0 = (const float*)d_in[4];
    const float* ar0 = (const float*)d_in[5];
    const float* b0  = (const float*)d_in[6];
    const float* W1  = (const float*)d_in[7];
    const float* al1 = (const float*)d_in[8];
    const float* ar1 = (const float*)d_in[9];
    const float* b1  = (const float*)d_in[10];
    const float* W2  = (const float*)d_in[11];
    const float* al2 = (const float*)d_in[12];
    const float* ar2 = (const float*)d_in[13];
    const float* b2  = (const float*)d_in[14];
    float* out = (float*)d_out;

    int n = NN;
    int E = in_sizes[1];

    float *feat2, *el, *er, *el2, *er2;
    __half *feath, *hh, *a0h, *w0h, *w1h, *w2h;
    int *deg, *cur, *rp, *esrc;
    cudaGetSymbolAddress((void**)&feath, g_feath);
    cudaGetSymbolAddress((void**)&hh, g_hh);
    cudaGetSymbolAddress((void**)&feat2, g_feat2);
    cudaGetSymbolAddress((void**)&el, g_el);
    cudaGetSymbolAddress((void**)&er, g_er);
    cudaGetSymbolAddress((void**)&el2, g_el2);
    cudaGetSymbolAddress((void**)&er2, g_er2);
    cudaGetSymbolAddress((void**)&a0h, g_a0h);
    cudaGetSymbolAddress((void**)&w0h, g_w0h);
    cudaGetSymbolAddress((void**)&w1h, g_w1h);
    cudaGetSymbolAddress((void**)&w2h, g_w2h);
    cudaGetSymbolAddress((void**)&deg, g_deg);
    cudaGetSymbolAddress((void**)&cur, g_cursor);
    cudaGetSymbolAddress((void**)&rp, g_rowptr);
    cudaGetSymbolAddress((void**)&esrc, g_esrc);

    static int attr_done = 0;
    if (!attr_done) {
        cudaFuncSetAttribute(k_mma_hh, cudaFuncAttributeMaxDynamicSharedMemorySize,
                             SMEM_BYTES);
        cudaFuncSetAttribute(k_mma_hf, cudaFuncAttributeMaxDynamicSharedMemorySize,
                             SMEM_BYTES);
        attr_done = 1;
    }

    // CSR by dst
    k_zero<<<(n + 255) / 256, 256>>>(deg, n);
    k_hist<<<(E + 255) / 256, 256>>>(dst, deg, E);
    k_scan<<<1, 1024>>>(deg, rp, cur, n);
    k_scatter<<<(E + 255) / 256, 256>>>(dst, src, cur, esrc, E);

    // convert GEMM inputs to fp16
    k_cvth<<<(NN * INF_ / 8 + 255) / 256, 256>>>(a0h, in_feat, NN * INF_ / 8);
    k_cvth<<<(INF_ * HID / 8 + 255) / 256, 256>>>(w0h, W0, INF_ * HID / 8);
    k_cvth<<<(HID * HID / 8 + 255) / 256, 256>>>(w1h, W1, HID * HID / 8);
    k_cvth<<<(HID * NCLS / 8 + 255) / 256, 256>>>(w2h, W2, HID * NCLS / 8);

    int nwarp_blocks = (n + 7) / 8;

    // layer 0
    {
        dim3 g((n + BM - 1) / BM, (HID + BN - 1) / BN);
        k_mma_hh<<<g, 256, SMEM_BYTES>>>(a0h, w0h, feath, n, HID, INF_);
        k_prep_h<<<nwarp_blocks, 256>>>(feath, al0, ar0, el, er, n);
        k_agg8<<<nwarp_blocks, 256>>>(feath, el, er, rp, esrc, b0, hh, n, 1);
    }
    // layer 1
    {
        dim3 g((n + BM - 1) / BM, (HID + BN - 1) / BN);
        k_mma_hh<<<g, 256, SMEM_BYTES>>>(hh, w1h, feath, n, HID, HID);
        k_prep_h<<<nwarp_blocks, 256>>>(feath, al1, ar1, el, er, n);
        k_agg8<<<nwarp_blocks, 256>>>(feath, el, er, rp, esrc, b1, hh, n, 1);
    }
    // output layer (1 head, 40 classes)
    {
        dim3 g((n + BM - 1) / BM, (NCLS + BN - 1) / BN);
        k_mma_hf<<<g, 256, SMEM_BYTES>>>(hh, w2h, feat2, n, NCLS, HID);
        k_elr1<<<nwarp_blocks, 256>>>(feat2, al2, ar2, el2, er2, n);
        k_agg1<<<nwarp_blocks, 256>>>(feat2, el2, er2, rp, esrc, b2, out, n);
    }
}

// round 12
// speedup vs baseline: 3.1593x; 1.0652x over previous
#include <cuda_runtime.h>
#include <cuda_fp16.h>
#include <float.h>
#include <stdint.h>

// Problem constants (fixed shapes)
#define NN 50000
#define NE 800000
#define INF_ 512
#define HID 256
#define NH 8
#define HD 32
#define NCLS 40
#define NEG_SLOPE 0.2f

// ---------------- scratch (device globals; no allocs allowed) ----------------
__device__ __align__(16) __half g_feath[NN * HID];   // fp16 activations (GEMM out / gather in)
__device__ __align__(16) __half g_hh[NN * HID];      // fp16 hidden activations (GEMM A)
__device__ __align__(16) float g_feat2[NN * NCLS];
__device__ __align__(16) float g_el[NN * NH];
__device__ __align__(16) float g_er[NN * NH];
__device__ __align__(16) float g_el2[NN];
__device__ __align__(16) float g_er2[NN];
__device__ __align__(16) __half g_a0h[NN * INF_];    // fp16 in_feat
__device__ __align__(16) __half g_w0h[INF_ * HID];   // fp16 weights
__device__ __align__(16) __half g_w1h[HID * HID];
__device__ __align__(16) __half g_w2h[HID * NCLS];
__device__ int g_deg[NN];
__device__ int g_cursor[NN];
__device__ int g_rowptr[NN + 1];
__device__ int g_esrc[NE];

// ---------------- bit casts ----------------
__device__ __forceinline__ uint32_t h2_to_u32(half2 h) {
    uint32_t u;
    memcpy(&u, &h, 4);
    return u;
}
__device__ __forceinline__ half2 u32_to_h2(uint32_t u) {
    half2 h;
    memcpy(&h, &u, 4);
    return h;
}

// ---------------- CSR build ----------------
__global__ void k_zero(int* p, int n) {
    int i = blockIdx.x * blockDim.x + threadIdx.x;
    if (i < n) p[i] = 0;
}

__global__ void k_hist(const int* __restrict__ dst, int* deg, int E) {
    int i = blockIdx.x * blockDim.x + threadIdx.x;
    if (i < E) atomicAdd(&deg[dst[i]], 1);
}

__global__ void k_scan(const int* __restrict__ deg, int* __restrict__ rowptr,
                       int* __restrict__ cursor, int n) {
    __shared__ int wsum[32];
    __shared__ int carry;
    int t = threadIdx.x, lane = t & 31, wid = t >> 5;
    if (t == 0) carry = 0;
    __syncthreads();
    for (int base = 0; base < n; base += blockDim.x) {
        int i = base + t;
        int v = (i < n) ? deg[i] : 0;
        int x = v;
#pragma unroll
        for (int o = 1; o < 32; o <<= 1) {
            int y = __shfl_up_sync(0xffffffffu, x, o);
            if (lane >= o) x += y;
        }
        if (lane == 31) wsum[wid] = x;
        __syncthreads();
        if (wid == 0) {
            int s = (lane < (int)(blockDim.x >> 5)) ? wsum[lane] : 0;
#pragma unroll
            for (int o = 1; o < 32; o <<= 1) {
                int y = __shfl_up_sync(0xffffffffu, s, o);
                if (lane >= o) s += y;
            }
            wsum[lane] = s;
        }
        __syncthreads();
        int woff = (wid == 0) ? 0 : wsum[wid - 1];
        int excl = carry + woff + x - v;
        if (i < n) { rowptr[i] = excl; cursor[i] = excl; }
        int total = wsum[(blockDim.x >> 5) - 1];
        __syncthreads();
        if (t == 0) carry += total;
        __syncthreads();
    }
    if (threadIdx.x == 0) rowptr[n] = carry;
}

__global__ void k_scatter(const int* __restrict__ dst, const int* __restrict__ src,
                          int* cursor, int* __restrict__ esrc, int E) {
    int i = blockIdx.x * blockDim.x + threadIdx.x;
    if (i < E) {
        int p = atomicAdd(&cursor[dst[i]], 1);
        esrc[p] = src[i];
    }
}

// ---------------- fp32 -> fp16 convert (8 elems/thread) ----------------
__global__ void k_cvth(__half* __restrict__ dst, const float* __restrict__ src, int n8) {
    int i = blockIdx.x * blockDim.x + threadIdx.x;
    if (i >= n8) return;
    float4 v0 = ((const float4*)src)[i * 2];
    float4 v1 = ((const float4*)src)[i * 2 + 1];
    uint4 pk;
    pk.x = h2_to_u32(__floats2half2_rn(v0.x, v0.y));
    pk.y = h2_to_u32(__floats2half2_rn(v0.z, v0.w));
    pk.z = h2_to_u32(__floats2half2_rn(v1.x, v1.y));
    pk.w = h2_to_u32(__floats2half2_rn(v1.z, v1.w));
    ((uint4*)dst)[i] = pk;
}

// ---------------- FP16 tensor-core GEMM core ----------------
#define BM 128
#define BN 128
#define BK 32
#define NSTAGE 4
#define ASTR 40
#define BSTR 136
#define A_ST_H (BM * ASTR)
#define B_ST_H (BK * BSTR)
#define SMEM_BYTES (NSTAGE * (A_ST_H + B_ST_H) * 2)

__device__ __forceinline__ void ldsm4(uint32_t* r, uint32_t addr) {
    asm volatile("ldmatrix.sync.aligned.m8n8.x4.shared.b16 {%0,%1,%2,%3}, [%4];"
                 : "=r"(r[0]), "=r"(r[1]), "=r"(r[2]), "=r"(r[3]) : "r"(addr));
}
__device__ __forceinline__ void ldsm4t(uint32_t* r, uint32_t addr) {
    asm volatile("ldmatrix.sync.aligned.m8n8.x4.trans.shared.b16 {%0,%1,%2,%3}, [%4];"
                 : "=r"(r[0]), "=r"(r[1]), "=r"(r[2]), "=r"(r[3]) : "r"(addr));
}
__device__ __forceinline__ void mma16(float* c, const uint32_t* a, const uint32_t* b) {
    asm volatile(
        "mma.sync.aligned.m16n8k16.row.col.f32.f16.f16.f32 "
        "{%0,%1,%2,%3}, {%4,%5,%6,%7}, {%8,%9}, {%0,%1,%2,%3};"
        : "+f"(c[0]), "+f"(c[1]), "+f"(c[2]), "+f"(c[3])
        : "r"(a[0]), "r"(a[1]), "r"(a[2]), "r"(a[3]), "r"(b[0]), "r"(b[1]));
}
__device__ __forceinline__ void cp16(uint32_t dst, const void* src, bool pred) {
    int sz = pred ? 16 : 0;
    asm volatile("cp.async.cg.shared.global [%0], [%1], 16, %2;"
                 :: "r"(dst), "l"(src), "r"(sz));
}
__device__ __forceinline__ void cp_commit() {
    asm volatile("cp.async.commit_group;");
}
template <int N>
__device__ __forceinline__ void cp_wait() {
    asm volatile("cp.async.wait_group %0;" :: "n"(N));
}

// Shared mainloop. OUT_HALF: fp16 C. DO_ELR: fuse el/er projection in epilogue
// (requires warp n-tile width == HD == 32 and N multiple of 128).
template <int OUT_HALF, int DO_ELR>
__device__ __forceinline__ void mma_body(const __half* __restrict__ A,
                                         const __half* __restrict__ B,
                                         void* __restrict__ Cv,
                                         int M, int N, int K,
                                         const float* __restrict__ al,
                                         const float* __restrict__ ar,
                                         float* __restrict__ el,
                                         float* __restrict__ er) {
    extern __shared__ __half smemh[];
    uint32_t sbase;
    asm("{ .reg .u64 t; cvta.to.shared.u64 t, %1; cvt.u32.u64 %0, t; }"
        : "=r"(sbase) : "l"(smemh));

    int tid = threadIdx.x;
    int warp = tid >> 5, lane = tid & 31;
    int gid = lane >> 2, tg = lane & 3;
    int wm = warp >> 2, wn = warp & 3;
    int m0 = blockIdx.x * BM, n0 = blockIdx.y * BN;

    int ar_ = tid >> 2;
    int ac = (tid & 3) * 8;
    int bk = tid >> 4;
    int bn = (tid & 15) * 8;
    bool bok = (n0 + bn + 8 <= N);

    float acc[4][4][4];
#pragma unroll
    for (int mi = 0; mi < 4; mi++)
#pragma unroll
        for (int ni = 0; ni < 4; ni++)
#pragma unroll
            for (int r = 0; r < 4; r++) acc[mi][ni][r] = 0.f;

    int kTiles = K / BK;

#define FILL_STAGE_H(s, kt)                                                            \
    do {                                                                               \
        int k0 = (kt) * BK;                                                            \
        uint32_t abase = sbase + (uint32_t)(s) * (A_ST_H * 2);                         \
        uint32_t bbase = sbase + (uint32_t)(NSTAGE * A_ST_H + (s) * B_ST_H) * 2;       \
        cp16(abase + (ar_ * ASTR + ac) * 2,                                            \
             A + (size_t)(m0 + ar_) * K + k0 + ac, m0 + ar_ < M);                      \
        cp16(abase + ((ar_ + 64) * ASTR + ac) * 2,                                     \
             A + (size_t)(m0 + ar_ + 64) * K + k0 + ac, m0 + ar_ + 64 < M);            \
        cp16(bbase + (bk * BSTR + bn) * 2,                                             \
             B + (size_t)(k0 + bk) * N + n0 + bn, bok);                                \
        cp16(bbase + ((bk + 16) * BSTR + bn) * 2,                                      \
             B + (size_t)(k0 + bk + 16) * N + n0 + bn, bok);                           \
    } while (0)

#pragma unroll
    for (int s = 0; s < NSTAGE - 1; s++) {
        if (s < kTiles) FILL_STAGE_H(s, s);
        cp_commit();
    }

    int lrow = lane & 7, lg = lane >> 3;

    for (int kt = 0; kt < kTiles; kt++) {
        cp_wait<NSTAGE - 2>();
        // single barrier per kt: separates prior iteration's reads of the
        // stage about to be refilled from this iteration's cp.async fill.
        __syncthreads();

        int nkt = kt + NSTAGE - 1;
        if (nkt < kTiles) FILL_STAGE_H(nkt % NSTAGE, nkt);
        cp_commit();

        int buf = kt % NSTAGE;
        uint32_t abase = sbase + (uint32_t)buf * (A_ST_H * 2);
        uint32_t bbase = sbase + (uint32_t)(NSTAGE * A_ST_H + buf * B_ST_H) * 2;

#pragma unroll
        for (int kstep = 0; kstep < 2; kstep++) {
            uint32_t af[4][4], bf[4][2];
            int colA = kstep * 16 + (lg >> 1) * 8;
#pragma unroll
            for (int mi = 0; mi < 4; mi++) {
                int row = wm * 64 + mi * 16 + (lg & 1) * 8 + lrow;
                ldsm4(af[mi], abase + (uint32_t)(row * ASTR + colA) * 2);
            }
            int rowB = kstep * 16 + (lg & 1) * 8 + lrow;
#pragma unroll
            for (int np = 0; np < 2; np++) {
                uint32_t t[4];
                int colB = wn * 32 + np * 16 + (lg >> 1) * 8;
                ldsm4t(t, bbase + (uint32_t)(rowB * BSTR + colB) * 2);
                bf[np * 2][0] = t[0]; bf[np * 2][1] = t[1];
                bf[np * 2 + 1][0] = t[2]; bf[np * 2 + 1][1] = t[3];
            }
#pragma unroll
            for (int mi = 0; mi < 4; mi++)
#pragma unroll
                for (int ni = 0; ni < 4; ni++) mma16(acc[mi][ni], af[mi], bf[ni]);
        }
    }

    // ---- C writeback ----
#pragma unroll
    for (int mi = 0; mi < 4; mi++) {
        int r0 = m0 + wm * 64 + mi * 16 + gid;
#pragma unroll
        for (int ni = 0; ni < 4; ni++) {
            int c0 = n0 + wn * 32 + ni * 8 + tg * 2;
            if (OUT_HALF) {
                __half* C = (__half*)Cv;
                if (r0 < M && c0 < N) {
                    half2 h = __floats2half2_rn(acc[mi][ni][0], acc[mi][ni][1]);
                    *(half2*)(C + (size_t)r0 * N + c0) = h;
                }
                if (r0 + 8 < M && c0 < N) {
                    half2 h = __floats2half2_rn(acc[mi][ni][2], acc[mi][ni][3]);
                    *(half2*)(C + (size_t)(r0 + 8) * N + c0) = h;
                }
            } else {
                float* C = (float*)Cv;
                if (r0 < M) {
                    if (c0 < N) C[(size_t)r0 * N + c0] = acc[mi][ni][0];
                    if (c0 + 1 < N) C[(size_t)r0 * N + c0 + 1] = acc[mi][ni][1];
                }
                if (r0 + 8 < M) {
                    if (c0 < N) C[(size_t)(r0 + 8) * N + c0] = acc[mi][ni][2];
                    if (c0 + 1 < N) C[(size_t)(r0 + 8) * N + c0 + 1] = acc[mi][ni][3];
                }
            }
        }
    }

    // ---- fused el/er projection ----
    // Warp's 32 cols = one head (head = n0/32 + wn). Quad (lanes sharing gid)
    // covers all 32 cols for rows r0/r0+8. Disjoint (node, head) across
    // blocks/warps -> plain stores.
    if (DO_ELR) {
        int head = (n0 >> 5) + wn;
        float alv[8], arv[8];
#pragma unroll
        for (int ni = 0; ni < 4; ni++) {
            int c0 = n0 + wn * 32 + ni * 8 + tg * 2;
            alv[ni * 2] = __ldg(al + c0); alv[ni * 2 + 1] = __ldg(al + c0 + 1);
            arv[ni * 2] = __ldg(ar + c0); arv[ni * 2 + 1] = __ldg(ar + c0 + 1);
        }
#pragma unroll
        for (int mi = 0; mi < 4; mi++) {
            float el0 = 0.f, el1 = 0.f, er0 = 0.f, er1 = 0.f;
#pragma unroll
            for (int ni = 0; ni < 4; ni++) {
                el0 += acc[mi][ni][0] * alv[ni * 2] + acc[mi][ni][1] * alv[ni * 2 + 1];
                el1 += acc[mi][ni][2] * alv[ni * 2] + acc[mi][ni][3] * alv[ni * 2 + 1];
                er0 += acc[mi][ni][0] * arv[ni * 2] + acc[mi][ni][1] * arv[ni * 2 + 1];
                er1 += acc[mi][ni][2] * arv[ni * 2] + acc[mi][ni][3] * arv[ni * 2 + 1];
            }
            // reduce across quad (tg bits = lane bits 0,1)
            el0 += __shfl_xor_sync(0xffffffffu, el0, 1);
            el0 += __shfl_xor_sync(0xffffffffu, el0, 2);
            el1 += __shfl_xor_sync(0xffffffffu, el1, 1);
            el1 += __shfl_xor_sync(0xffffffffu, el1, 2);
            er0 += __shfl_xor_sync(0xffffffffu, er0, 1);
            er0 += __shfl_xor_sync(0xffffffffu, er0, 2);
            er1 += __shfl_xor_sync(0xffffffffu, er1, 1);
            er1 += __shfl_xor_sync(0xffffffffu, er1, 2);
            if (tg == 0) {
                int r0 = m0 + wm * 64 + mi * 16 + gid;
                if (r0 < M) { el[r0 * NH + head] = el0; er[r0 * NH + head] = er0; }
                if (r0 + 8 < M) { el[(r0 + 8) * NH + head] = el1; er[(r0 + 8) * NH + head] = er1; }
            }
        }
    }
}

__global__ void __launch_bounds__(256) k_mma_hh_elr(const __half* __restrict__ A,
                                                    const __half* __restrict__ B,
                                                    __half* __restrict__ C,
                                                    int M, int N, int K,
                                                    const float* __restrict__ al,
                                                    const float* __restrict__ ar,
                                                    float* __restrict__ el,
                                                    float* __restrict__ er) {
    mma_body<1, 1>(A, B, C, M, N, K, al, ar, el, er);
}
__global__ void __launch_bounds__(256) k_mma_hf(const __half* __restrict__ A,
                                                const __half* __restrict__ B,
                                                float* __restrict__ C,
                                                int M, int N, int K) {
    mma_body<0, 0>(A, B, C, M, N, K, nullptr, nullptr, nullptr, nullptr);
}

// ---------------- helpers ----------------
__device__ __forceinline__ float warp_sum(float v) {
#pragma unroll
    for (int o = 16; o > 0; o >>= 1) v += __shfl_xor_sync(0xffffffffu, v, o);
    return v;
}
__device__ __forceinline__ float leaky(float x) { return x > 0.f ? x : NEG_SLOPE * x; }

__global__ void k_elr1(const float* __restrict__ feat2, const float* __restrict__ al,
                       const float* __restrict__ ar, float* __restrict__ el,
                       float* __restrict__ er, int n) {
    int w = (blockIdx.x * blockDim.x + threadIdx.x) >> 5;
    int lane = threadIdx.x & 31;
    if (w >= n) return;
    const float* f = feat2 + (size_t)w * NCLS;
    float sl = f[lane] * __ldg(al + lane);
    float sr = f[lane] * __ldg(ar + lane);
    if (lane < 8) {
        sl += f[32 + lane] * __ldg(al + 32 + lane);
        sr += f[32 + lane] * __ldg(ar + 32 + lane);
    }
    sl = warp_sum(sl);
    sr = warp_sum(sr);
    if (lane == 0) { el[w] = sl; er[w] = sr; }
}

// ---------------- aggregation: warp per dst node, inline softmax weights ----------------
__global__ void k_agg8(const __half* __restrict__ feath, const float* __restrict__ el,
                       const float* __restrict__ er, const int* __restrict__ rowptr,
                       const int* __restrict__ esrc, const float* __restrict__ bias,
                       __half* __restrict__ out, int n, int do_relu) {
    int node = (blockIdx.x * blockDim.x + threadIdx.x) >> 5;
    int lane = threadIdx.x & 31;
    if (node >= n) return;
    int beg = rowptr[node], end = rowptr[node + 1];
    int head = lane >> 2;
    int col = lane * 8;
    float ern = __ldg(er + node * NH + head);

    float acc[8];
#pragma unroll
    for (int r = 0; r < 8; r++) acc[r] = 0.f;
    float den = 0.f;

#pragma unroll 4
    for (int i = beg; i < end; i++) {
        int s = esrc[i];  // warp-uniform
        float w = __expf(leaky(__ldg(el + s * NH + head) + ern));
        den += w;
        uint4 pk = *((const uint4*)(feath + (size_t)s * HID + col));
        float2 f0 = __half22float2(u32_to_h2(pk.x));
        float2 f1 = __half22float2(u32_to_h2(pk.y));
        float2 f2 = __half22float2(u32_to_h2(pk.z));
        float2 f3 = __half22float2(u32_to_h2(pk.w));
        acc[0] = fmaf(w, f0.x, acc[0]); acc[1] = fmaf(w, f0.y, acc[1]);
        acc[2] = fmaf(w, f1.x, acc[2]); acc[3] = fmaf(w, f1.y, acc[3]);
        acc[4] = fmaf(w, f2.x, acc[4]); acc[5] = fmaf(w, f2.y, acc[5]);
        acc[6] = fmaf(w, f3.x, acc[6]); acc[7] = fmaf(w, f3.y, acc[7]);
    }
    float inv = 1.f / fmaxf(den, 1e-9f);
    float4 b0 = *(const float4*)(bias + col);
    float4 b1 = *(const float4*)(bias + col + 4);
    float ob[8] = {b0.x, b0.y, b0.z, b0.w, b1.x, b1.y, b1.z, b1.w};
    float o[8];
#pragma unroll
    for (int r = 0; r < 8; r++) {
        float v = fmaf(acc[r], inv, ob[r]);
        if (do_relu) v = fmaxf(v, 0.f);
        o[r] = v;
    }
    uint4 pk;
    pk.x = h2_to_u32(__floats2half2_rn(o[0], o[1]));
    pk.y = h2_to_u32(__floats2half2_rn(o[2], o[3]));
    pk.z = h2_to_u32(__floats2half2_rn(o[4], o[5]));
    pk.w = h2_to_u32(__floats2half2_rn(o[6], o[7]));
    *((uint4*)(out + (size_t)node * HID + col)) = pk;
}

// output layer: 1 head, 40 dims; lane<10 owns float4 cols [lane*4, lane*4+4)
__global__ void k_agg1(const float* __restrict__ feat2, const float* __restrict__ el,
                       const float* __restrict__ er, const int* __restrict__ rowptr,
                       const int* __restrict__ esrc, const float* __restrict__ bias,
                       float* __restrict__ out, int n) {
    int node = (blockIdx.x * blockDim.x + threadIdx.x) >> 5;
    int lane = threadIdx.x & 31;
    if (node >= n) return;
    int beg = rowptr[node], end = rowptr[node + 1];
    float ern = er[node];

    float4 acc = make_float4(0.f, 0.f, 0.f, 0.f);
    float den = 0.f;
#pragma unroll 4
    for (int i = beg; i < end; i++) {
        int s = esrc[i];
        float w = __expf(leaky(__ldg(el + s) + ern));
        den += w;
        if (lane < 10) {
            float4 f = *(const float4*)(feat2 + (size_t)s * NCLS + lane * 4);
            acc.x = fmaf(w, f.x, acc.x); acc.y = fmaf(w, f.y, acc.y);
            acc.z = fmaf(w, f.z, acc.z); acc.w = fmaf(w, f.w, acc.w);
        }
    }
    float inv = 1.f / fmaxf(den, 1e-9f);
    if (lane < 10) {
        float4 b = *(const float4*)(bias + lane * 4);
        float4 o;
        o.x = fmaf(acc.x, inv, b.x); o.y = fmaf(acc.y, inv, b.y);
        o.z = fmaf(acc.z, inv, b.z); o.w = fmaf(acc.w, inv, b.w);
        *(float4*)(out + (size_t)node * NCLS + lane * 4) = o;
    }
}

// ---------------- host ----------------
extern "C" void kernel_launch(void* const* d_in, const int* in_sizes, int n_in,
                              void* d_out, int out_size) {
    const float* in_feat = (const float*)d_in[0];
    const int*   src     = (const int*)d_in[1];
    const int*   dst     = (const int*)d_in[2];
    const float* W0  = (const float*)d_in[3];
    const float* al0 = (const float*)d_in[4];
    const float* ar0 = (const float*)d_in[5];
    const float* b0  = (const float*)d_in[6];
    const float* W1  = (const float*)d_in[7];
    const float* al1 = (const float*)d_in[8];
    const float* ar1 = (const float*)d_in[9];
    const float* b1  = (const float*)d_in[10];
    const float* W2  = (const float*)d_in[11];
    const float* al2 = (const float*)d_in[12];
    const float* ar2 = (const float*)d_in[13];
    const float* b2  = (const float*)d_in[14];
    float* out = (float*)d_out;

    int n = NN;
    int E = in_sizes[1];

    float *feat2, *el, *er, *el2, *er2;
    __half *feath, *hh, *a0h, *w0h, *w1h, *w2h;
    int *deg, *cur, *rp, *esrc;
    cudaGetSymbolAddress((void**)&feath, g_feath);
    cudaGetSymbolAddress((void**)&hh, g_hh);
    cudaGetSymbolAddress((void**)&feat2, g_feat2);
    cudaGetSymbolAddress((void**)&el, g_el);
    cudaGetSymbolAddress((void**)&er, g_er);
    cudaGetSymbolAddress((void**)&el2, g_el2);
    cudaGetSymbolAddress((void**)&er2, g_er2);
    cudaGetSymbolAddress((void**)&a0h, g_a0h);
    cudaGetSymbolAddress((void**)&w0h, g_w0h);
    cudaGetSymbolAddress((void**)&w1h, g_w1h);
    cudaGetSymbolAddress((void**)&w2h, g_w2h);
    cudaGetSymbolAddress((void**)&deg, g_deg);
    cudaGetSymbolAddress((void**)&cur, g_cursor);
    cudaGetSymbolAddress((void**)&rp, g_rowptr);
    cudaGetSymbolAddress((void**)&esrc, g_esrc);

    static int attr_done = 0;
    if (!attr_done) {
        cudaFuncSetAttribute(k_mma_hh_elr, cudaFuncAttributeMaxDynamicSharedMemorySize,
                             SMEM_BYTES);
        cudaFuncSetAttribute(k_mma_hf, cudaFuncAttributeMaxDynamicSharedMemorySize,
                             SMEM_BYTES);
        attr_done = 1;
    }

    // CSR by dst
    k_zero<<<(n + 255) / 256, 256>>>(deg, n);
    k_hist<<<(E + 255) / 256, 256>>>(dst, deg, E);
    k_scan<<<1, 1024>>>(deg, rp, cur, n);
    k_scatter<<<(E + 255) / 256, 256>>>(dst, src, cur, esrc, E);

    // convert GEMM inputs to fp16
    k_cvth<<<(NN * INF_ / 8 + 255) / 256, 256>>>(a0h, in_feat, NN * INF_ / 8);
    k_cvth<<<(INF_ * HID / 8 + 255) / 256, 256>>>(w0h, W0, INF_ * HID / 8);
    k_cvth<<<(HID * HID / 8 + 255) / 256, 256>>>(w1h, W1, HID * HID / 8);
    k_cvth<<<(HID * NCLS / 8 + 255) / 256, 256>>>(w2h, W2, HID * NCLS / 8);

    int nwarp_blocks = (n + 7) / 8;

    // layer 0 (GEMM + fused el/er)
    {
        dim3 g((n + BM - 1) / BM, (HID + BN - 1) / BN);
        k_mma_hh_elr<<<g, 256, SMEM_BYTES>>>(a0h, w0h, feath, n, HID, INF_,
                                             al0, ar0, el, er);
        k_agg8<<<nwarp_blocks, 256>>>(feath, el, er, rp, esrc, b0, hh, n, 1);
    }
    // layer 1
    {
        dim3 g((n + BM - 1) / BM, (HID + BN - 1) / BN);
        k_mma_hh_elr<<<g, 256, SMEM_BYTES>>>(hh, w1h, feath, n, HID, HID,
                                             al1, ar1, el, er);
        k_agg8<<<nwarp_blocks, 256>>>(feath, el, er, rp, esrc, b1, hh, n, 1);
    }
    // output layer (1 head, 40 classes)
    {
        dim3 g((n + BM - 1) / BM, (NCLS + BN - 1) / BN);
        k_mma_hf<<<g, 256, SMEM_BYTES>>>(hh, w2h, feat2, n, NCLS, HID);
        k_elr1<<<nwarp_blocks, 256>>>(feat2, al2, ar2, el2, er2, n);
        k_agg1<<<nwarp_blocks, 256>>>(feat2, el2, er2, rp, esrc, b2, out, n);
    }
}